// round 1
// baseline (speedup 1.0000x reference)
#include <cuda_runtime.h>

// Problem constants
#define BB  2
#define SS  2048
#define DDm 1024
#define HH  16
#define DK  64
#define MT  (BB*SS)      // 4096 rows in (b,s)-flattened matrices

// Scratch (allocation-free: __device__ globals)
__device__ float g_Q[BB*HH*SS*DK];
__device__ float g_K[BB*HH*SS*DK];
__device__ float g_V[BB*HH*SS*DK];
__device__ float g_ctx[BB*SS*DDm];

// ---------------------------------------------------------------------------
// NT GEMM: C = A[M,K] @ W[N,K]^T + bias[N]
// MODE 0: write C in split-head layout [B,H,S,DK] (for q/k/v projections)
// MODE 1: write C plain row-major [M,N]
// 128x128 tile, BK=8, 256 threads, 8x8 per-thread microtile, reg prefetch.
// ---------------------------------------------------------------------------
template<int MODE>
__global__ void __launch_bounds__(256) gemm_nt_kernel(
    const float* __restrict__ A, const float* __restrict__ W,
    const float* __restrict__ bias, float* __restrict__ C,
    int M, int N, int K)
{
    constexpr int BM = 128, BN = 128, BK = 8;
    __shared__ __align__(16) float As[BK][BM + 4];
    __shared__ __align__(16) float Bs[BK][BN + 4];

    const int tid = threadIdx.x;
    const int tx  = tid & 15;
    const int ty  = tid >> 4;
    const int m0  = blockIdx.y * BM;
    const int n0  = blockIdx.x * BN;

    // loader mapping: one float4 of A and one of W per thread per k-tile
    const int lm = tid >> 1;          // row within tile (0..127)
    const int lk = (tid & 1) * 4;     // k offset (0 or 4)
    const float* Ap = A + (size_t)(m0 + lm) * K + lk;
    const float* Wp = W + (size_t)(n0 + lm) * K + lk;

    float acc[8][8];
#pragma unroll
    for (int i = 0; i < 8; i++)
#pragma unroll
        for (int j = 0; j < 8; j++) acc[i][j] = 0.0f;

    float4 pa = *(const float4*)Ap;
    float4 pb = *(const float4*)Wp;

    for (int k0 = 0; k0 < K; k0 += BK) {
        As[lk + 0][lm] = pa.x; As[lk + 1][lm] = pa.y;
        As[lk + 2][lm] = pa.z; As[lk + 3][lm] = pa.w;
        Bs[lk + 0][lm] = pb.x; Bs[lk + 1][lm] = pb.y;
        Bs[lk + 2][lm] = pb.z; Bs[lk + 3][lm] = pb.w;
        __syncthreads();

        const int kn = k0 + BK;
        if (kn < K) {
            pa = *(const float4*)(Ap + kn);
            pb = *(const float4*)(Wp + kn);
        }

#pragma unroll
        for (int k = 0; k < BK; k++) {
            float4 a0 = *(const float4*)&As[k][ty * 8];
            float4 a1 = *(const float4*)&As[k][ty * 8 + 4];
            float4 b0 = *(const float4*)&Bs[k][tx * 8];
            float4 b1 = *(const float4*)&Bs[k][tx * 8 + 4];
            float av[8] = {a0.x, a0.y, a0.z, a0.w, a1.x, a1.y, a1.z, a1.w};
            float bv[8] = {b0.x, b0.y, b0.z, b0.w, b1.x, b1.y, b1.z, b1.w};
#pragma unroll
            for (int i = 0; i < 8; i++)
#pragma unroll
                for (int j = 0; j < 8; j++)
                    acc[i][j] = fmaf(av[i], bv[j], acc[i][j]);
        }
        __syncthreads();
    }

    // epilogue
#pragma unroll
    for (int i = 0; i < 8; i++) {
        const int m = m0 + ty * 8 + i;
        const int n = n0 + tx * 8;
        float o[8];
#pragma unroll
        for (int j = 0; j < 8; j++) o[j] = acc[i][j] + bias[n + j];

        float* dst;
        if (MODE == 0) {
            // m = b*SS + s ; n = h*DK + dk  ->  [b][h][s][dk]
            const int b  = m >> 11;          // SS = 2048
            const int s  = m & (SS - 1);
            const int h  = n >> 6;           // DK = 64
            const int dk = n & 63;
            dst = C + (((size_t)(b * HH + h) * SS + s) * DK + dk);
        } else {
            dst = C + (size_t)m * N + n;
        }
        *(float4*)dst       = make_float4(o[0], o[1], o[2], o[3]);
        *(float4*)(dst + 4) = make_float4(o[4], o[5], o[6], o[7]);
    }
}

// ---------------------------------------------------------------------------
// Flash attention, fp32. One block per (b, h, 64-row q tile). 256 threads.
// Q,K staged transposed (d-major) with XOR swizzle; V natural; P reuses K buf.
// ---------------------------------------------------------------------------
__device__ __forceinline__ int swz(int row, int col) {
    // word index in a 64x64 tile stored row-major (row = d), 4-word XOR swizzle
    return (row << 6) + ((((col >> 2) ^ (row & 15)) << 2) | (col & 3));
}

__global__ void __launch_bounds__(256) attn_kernel(
    const float* __restrict__ Q, const float* __restrict__ K,
    const float* __restrict__ V, float* __restrict__ ctx)
{
    __shared__ __align__(16) float Qt [64 * 64];  // [d][r], swizzled
    __shared__ __align__(16) float KtP[64 * 64];  // [d][c] swizzled, then P[r][c]
    __shared__ __align__(16) float Vs [64 * 64];  // [c][d] plain

    const int qt = blockIdx.x;
    const int h  = blockIdx.y;
    const int b  = blockIdx.z;
    const int q0 = qt * 64;

    const size_t bh = ((size_t)b * HH + h) * SS * DK;
    const float* Qp = Q + bh + (size_t)q0 * DK;
    const float* Kp = K + bh;
    const float* Vp = V + bh;

    const int tid = threadIdx.x;
    const int tx  = tid & 15;
    const int ty  = tid >> 4;

    // stage Q transposed + swizzled
#pragma unroll
    for (int p = 0; p < 4; p++) {
        const int idx = tid + p * 256;
        const int r   = idx & 63;
        const int d4  = (idx >> 6) << 2;
        float4 v = *(const float4*)(Qp + (r << 6) + d4);
        Qt[swz(d4 + 0, r)] = v.x;
        Qt[swz(d4 + 1, r)] = v.y;
        Qt[swz(d4 + 2, r)] = v.z;
        Qt[swz(d4 + 3, r)] = v.w;
    }

    float m_i[4], l_i[4], acc[4][4];
#pragma unroll
    for (int i = 0; i < 4; i++) {
        m_i[i] = -1e30f; l_i[i] = 0.0f;
#pragma unroll
        for (int j = 0; j < 4; j++) acc[i][j] = 0.0f;
    }

    const int ktmax = qt + 1;   // causal: only tiles with keys <= query tile
    for (int kt = 0; kt < ktmax; kt++) {
        const float* Kb = Kp + kt * (64 * DK);
        const float* Vb = Vp + kt * (64 * DK);

        // load K (transposed+swizzled) and V (plain) tiles
#pragma unroll
        for (int p = 0; p < 4; p++) {
            const int idx = tid + p * 256;
            const int c   = idx & 63;
            const int d4  = (idx >> 6) << 2;
            float4 kv = *(const float4*)(Kb + (c << 6) + d4);
            KtP[swz(d4 + 0, c)] = kv.x;
            KtP[swz(d4 + 1, c)] = kv.y;
            KtP[swz(d4 + 2, c)] = kv.z;
            KtP[swz(d4 + 3, c)] = kv.w;
            *(float4*)(Vs + idx * 4) = *(const float4*)(Vb + idx * 4);
        }
        __syncthreads();

        // phase 1: S = Q @ K^T  (4x4 per thread)
        float s[4][4];
#pragma unroll
        for (int i = 0; i < 4; i++)
#pragma unroll
            for (int j = 0; j < 4; j++) s[i][j] = 0.0f;

#pragma unroll 16
        for (int d = 0; d < 64; d++) {
            const float4 a  = *(const float4*)&Qt [(d << 6) + ((ty ^ (d & 15)) << 2)];
            const float4 bk = *(const float4*)&KtP[(d << 6) + ((tx ^ (d & 15)) << 2)];
            const float av[4] = {a.x,  a.y,  a.z,  a.w};
            const float bw[4] = {bk.x, bk.y, bk.z, bk.w};
#pragma unroll
            for (int i = 0; i < 4; i++)
#pragma unroll
                for (int j = 0; j < 4; j++)
                    s[i][j] = fmaf(av[i], bw[j], s[i][j]);
        }
        __syncthreads();   // all Kt reads done; KtP can be rewritten as P

        // online softmax (rows of this thread: q0 + ty*4 + i)
#pragma unroll
        for (int i = 0; i < 4; i++) {
            const int qrow  = q0 + ty * 4 + i;
            const int kbase = kt * 64 + tx * 4;
            float sv[4];
#pragma unroll
            for (int j = 0; j < 4; j++)
                sv[j] = (kbase + j <= qrow) ? s[i][j] * 0.125f : -1e9f;

            float mx = fmaxf(fmaxf(sv[0], sv[1]), fmaxf(sv[2], sv[3]));
#pragma unroll
            for (int off = 1; off < 16; off <<= 1)
                mx = fmaxf(mx, __shfl_xor_sync(0xffffffffu, mx, off));

            const float mnew  = fmaxf(m_i[i], mx);
            const float alpha = __expf(m_i[i] - mnew);
            float rs = 0.0f;
#pragma unroll
            for (int j = 0; j < 4; j++) { sv[j] = __expf(sv[j] - mnew); rs += sv[j]; }
#pragma unroll
            for (int off = 1; off < 16; off <<= 1)
                rs += __shfl_xor_sync(0xffffffffu, rs, off);

            l_i[i] = l_i[i] * alpha + rs;
            m_i[i] = mnew;
#pragma unroll
            for (int j = 0; j < 4; j++) acc[i][j] *= alpha;

            *(float4*)&KtP[(ty * 4 + i) * 64 + tx * 4] =
                make_float4(sv[0], sv[1], sv[2], sv[3]);
        }
        __syncthreads();

        // phase 2: acc += P @ V (rows ty*4+i, cols tx*4+j)
#pragma unroll 8
        for (int c = 0; c < 64; c++) {
            const float4 bv4 = *(const float4*)&Vs[(c << 6) + (tx << 2)];
            const float aw[4] = {
                KtP[(ty * 4 + 0) * 64 + c],
                KtP[(ty * 4 + 1) * 64 + c],
                KtP[(ty * 4 + 2) * 64 + c],
                KtP[(ty * 4 + 3) * 64 + c]
            };
            const float bw[4] = {bv4.x, bv4.y, bv4.z, bv4.w};
#pragma unroll
            for (int i = 0; i < 4; i++)
#pragma unroll
                for (int j = 0; j < 4; j++)
                    acc[i][j] = fmaf(aw[i], bw[j], acc[i][j]);
        }
        __syncthreads();
    }

    // epilogue: ctx[b][s][h*64 + d] = acc / l
#pragma unroll
    for (int i = 0; i < 4; i++) {
        const float inv = 1.0f / l_i[i];
        const int srow  = q0 + ty * 4 + i;
        float* dst = ctx + ((size_t)b * SS + srow) * DDm + h * DK + tx * 4;
        *(float4*)dst = make_float4(acc[i][0] * inv, acc[i][1] * inv,
                                    acc[i][2] * inv, acc[i][3] * inv);
    }
}

// ---------------------------------------------------------------------------
extern "C" void kernel_launch(void* const* d_in, const int* in_sizes, int n_in,
                              void* d_out, int out_size)
{
    const float* q  = (const float*)d_in[0];
    const float* k  = (const float*)d_in[1];
    const float* v  = (const float*)d_in[2];
    // d_in[3] = mask (int32 causal tril) — causal structure applied directly
    const float* wq = (const float*)d_in[4];
    const float* bq = (const float*)d_in[5];
    const float* wk = (const float*)d_in[6];
    const float* bk = (const float*)d_in[7];
    const float* wv = (const float*)d_in[8];
    const float* bv = (const float*)d_in[9];
    const float* wo = (const float*)d_in[10];
    const float* bo = (const float*)d_in[11];
    float* out = (float*)d_out;

    float *gq, *gk, *gv, *gctx;
    cudaGetSymbolAddress((void**)&gq,  g_Q);
    cudaGetSymbolAddress((void**)&gk,  g_K);
    cudaGetSymbolAddress((void**)&gv,  g_V);
    cudaGetSymbolAddress((void**)&gctx, g_ctx);

    const dim3 gg(DDm / 128, MT / 128);   // (8, 32)
    gemm_nt_kernel<0><<<gg, 256>>>(q, wq, bq, gq, MT, DDm, DDm);
    gemm_nt_kernel<0><<<gg, 256>>>(k, wk, bk, gk, MT, DDm, DDm);
    gemm_nt_kernel<0><<<gg, 256>>>(v, wv, bv, gv, MT, DDm, DDm);

    attn_kernel<<<dim3(SS / 64, HH, BB), 256>>>(gq, gk, gv, gctx);

    gemm_nt_kernel<1><<<gg, 256>>>(gctx, wo, bo, out, MT, DDm, DDm);
}

// round 3
// speedup vs baseline: 1.4664x; 1.4664x over previous
#include <cuda_runtime.h>
#include <cuda_bf16.h>
#include <cstdint>

// Problem constants
#define BB  2
#define SS  2048
#define DDm 1024
#define HH  16
#define DK  64
#define MT  (BB*SS)      // 4096

// Scratch (allocation-free: __device__ globals)
__device__ float g_Q[BB*HH*SS*DK];
__device__ float g_K[BB*HH*SS*DK];
__device__ float g_V[BB*HH*SS*DK];
__device__ float g_ctx[BB*SS*DDm];
__device__ __nv_bfloat16 g_Ah[MT*DDm];
__device__ __nv_bfloat16 g_Al[MT*DDm];
__device__ __nv_bfloat16 g_Wh[DDm*DDm];
__device__ __nv_bfloat16 g_Wl[DDm*DDm];

// ---------------------------------------------------------------------------
// helpers
// ---------------------------------------------------------------------------
__device__ __forceinline__ uint32_t smem_u32(const void* p) {
    uint32_t a;
    asm("{ .reg .u64 t; cvta.to.shared.u64 t, %1; cvt.u32.u64 %0, t; }"
        : "=r"(a) : "l"(p));
    return a;
}

__device__ __forceinline__ void cp16(uint32_t saddr, const void* gaddr) {
    asm volatile("cp.async.cg.shared.global [%0], [%1], 16;"
                 :: "r"(saddr), "l"(gaddr));
}

__device__ __forceinline__ void ldsm4(uint32_t* r, uint32_t addr) {
    asm volatile("ldmatrix.sync.aligned.m8n8.x4.shared.b16 {%0,%1,%2,%3}, [%4];"
                 : "=r"(r[0]), "=r"(r[1]), "=r"(r[2]), "=r"(r[3]) : "r"(addr));
}

__device__ __forceinline__ void mma_bf16(float* c, const uint32_t* a,
                                         const uint32_t* b) {
    asm volatile(
        "mma.sync.aligned.m16n8k16.row.col.f32.bf16.bf16.f32 "
        "{%0,%1,%2,%3}, {%4,%5,%6,%7}, {%8,%9}, {%0,%1,%2,%3};"
        : "+f"(c[0]), "+f"(c[1]), "+f"(c[2]), "+f"(c[3])
        : "r"(a[0]), "r"(a[1]), "r"(a[2]), "r"(a[3]), "r"(b[0]), "r"(b[1]));
}

// ---------------------------------------------------------------------------
// hi/lo bf16 split: h = rn(x), l = rn(x - h)
// ---------------------------------------------------------------------------
__global__ void __launch_bounds__(256) split_kernel(
    const float4* __restrict__ x,
    __nv_bfloat162* __restrict__ hi, __nv_bfloat162* __restrict__ lo, int n4)
{
    int i = blockIdx.x * blockDim.x + threadIdx.x;
    if (i >= n4) return;
    float4 v = x[i];
    __nv_bfloat16 h0 = __float2bfloat16_rn(v.x);
    __nv_bfloat16 h1 = __float2bfloat16_rn(v.y);
    __nv_bfloat16 h2 = __float2bfloat16_rn(v.z);
    __nv_bfloat16 h3 = __float2bfloat16_rn(v.w);
    __nv_bfloat16 l0 = __float2bfloat16_rn(v.x - __bfloat162float(h0));
    __nv_bfloat16 l1 = __float2bfloat16_rn(v.y - __bfloat162float(h1));
    __nv_bfloat16 l2 = __float2bfloat16_rn(v.z - __bfloat162float(h2));
    __nv_bfloat16 l3 = __float2bfloat16_rn(v.w - __bfloat162float(h3));
    hi[2*i]   = __halves2bfloat162(h0, h1);
    hi[2*i+1] = __halves2bfloat162(h2, h3);
    lo[2*i]   = __halves2bfloat162(l0, l1);
    lo[2*i+1] = __halves2bfloat162(l2, l3);
}

// ---------------------------------------------------------------------------
// HMMA GEMM: C = Ah@Wh^T + Ah@Wl^T + Al@Wh^T + bias (bf16 in, fp32 acc)
// A[M,K], W[N,K] row-major bf16. CTA 128x128, BK=32, 8 warps (64x32 each),
// cp.async double buffer. Smem rows padded to 80B (conflict-free ldmatrix).
// MODE 0: write split-head [B,H,S,DK]; MODE 1: plain [M,N].
// ---------------------------------------------------------------------------
#define TILE_B   10240              // 128 rows * 80 B
#define STAGE_B  (4 * TILE_B)       // Ah, Al, Wh, Wl
#define GEMM_SMEM (2 * STAGE_B)     // 81920

template<int MODE>
__global__ void __launch_bounds__(256) gemm_mma(
    const __nv_bfloat16* __restrict__ Ah, const __nv_bfloat16* __restrict__ Al,
    const __nv_bfloat16* __restrict__ Wh, const __nv_bfloat16* __restrict__ Wl,
    const float* __restrict__ bias, float* __restrict__ C,
    int M, int N, int K)
{
    extern __shared__ __align__(16) char smem[];
    const uint32_t sbase = smem_u32(smem);

    const int tid  = threadIdx.x;
    const int lane = tid & 31;
    const int wid  = tid >> 5;
    const int wr   = wid >> 2;        // 0..1
    const int wc   = wid & 3;         // 0..3
    const int m0   = blockIdx.y * 128;
    const int n0   = blockIdx.x * 128;

    float acc[4][4][4];
#pragma unroll
    for (int i = 0; i < 4; i++)
#pragma unroll
        for (int j = 0; j < 4; j++)
#pragma unroll
            for (int r = 0; r < 4; r++) acc[i][j][r] = 0.0f;

    // loader: 4 tiles * 512 x 16B, 8 cp.async per thread per chunk
    auto load_chunk = [&](int i, int buf) {
        const int kc0 = i * 32;
        const uint32_t stage = sbase + (uint32_t)buf * STAGE_B;
#pragma unroll
        for (int t = 0; t < 4; t++) {
            const __nv_bfloat16* src = (t == 0) ? Ah : (t == 1) ? Al
                                     : (t == 2) ? Wh : Wl;
            const int r0 = (t < 2) ? m0 : n0;
#pragma unroll
            for (int h = 0; h < 2; h++) {
                const int idx = tid + h * 256;
                const int row = idx >> 2, c = idx & 3;
                cp16(stage + t * TILE_B + row * 80 + c * 16,
                     src + (size_t)(r0 + row) * K + kc0 + c * 8);
            }
        }
    };

    // per-thread ldmatrix address components
    const int mid   = lane >> 3;          // matrix id 0..3
    const int lr    = lane & 7;
    const int a_moff = (mid & 1) * 8;     // A: m offset per matrix
    const int a_koff = (mid >> 1) * 8;    // A: k offset per matrix
    const int b_noff = (mid >> 1) * 8;    // B: n offset per matrix
    const int b_koff = (mid & 1) * 8;     // B: k offset per matrix

    const int NCH = K / 32;               // 32

    load_chunk(0, 0);
    asm volatile("cp.async.commit_group;" ::: "memory");

    for (int i = 0; i < NCH; i++) {
        if (i + 1 < NCH) {
            load_chunk(i + 1, (i + 1) & 1);
            asm volatile("cp.async.commit_group;" ::: "memory");
            asm volatile("cp.async.wait_group 1;" ::: "memory");
        } else {
            asm volatile("cp.async.wait_group 0;" ::: "memory");
        }
        __syncthreads();

        const uint32_t stage = sbase + (uint32_t)(i & 1) * STAGE_B;
        const uint32_t tAh = stage;
        const uint32_t tAl = stage + TILE_B;
        const uint32_t tWh = stage + 2 * TILE_B;
        const uint32_t tWl = stage + 3 * TILE_B;

#pragma unroll
        for (int ks = 0; ks < 2; ks++) {
            uint32_t ah[4][4], al[4][4], bh[4][2], bl[4][2];
#pragma unroll
            for (int mt = 0; mt < 4; mt++) {
                const int r  = wr * 64 + mt * 16 + a_moff + lr;
                const int kc = ks * 16 + a_koff;
                ldsm4(ah[mt], tAh + r * 80 + kc * 2);
                ldsm4(al[mt], tAl + r * 80 + kc * 2);
            }
#pragma unroll
            for (int np = 0; np < 2; np++) {
                const int r  = wc * 32 + np * 16 + b_noff + lr;
                const int kc = ks * 16 + b_koff;
                uint32_t t4[4];
                ldsm4(t4, tWh + r * 80 + kc * 2);
                bh[2*np][0] = t4[0]; bh[2*np][1] = t4[1];
                bh[2*np+1][0] = t4[2]; bh[2*np+1][1] = t4[3];
                ldsm4(t4, tWl + r * 80 + kc * 2);
                bl[2*np][0] = t4[0]; bl[2*np][1] = t4[1];
                bl[2*np+1][0] = t4[2]; bl[2*np+1][1] = t4[3];
            }
#pragma unroll
            for (int mt = 0; mt < 4; mt++)
#pragma unroll
                for (int nt = 0; nt < 4; nt++) {
                    mma_bf16(acc[mt][nt], ah[mt], bh[nt]);
                    mma_bf16(acc[mt][nt], ah[mt], bl[nt]);
                    mma_bf16(acc[mt][nt], al[mt], bh[nt]);
                }
        }
        __syncthreads();
    }

    // epilogue: d fragment -> global (float2 per piece), add bias
    const int g  = lane >> 2;
    const int t4 = lane & 3;
#pragma unroll
    for (int mt = 0; mt < 4; mt++) {
#pragma unroll
        for (int nt = 0; nt < 4; nt++) {
            const int col = n0 + wc * 32 + nt * 8 + t4 * 2;
            const float bx = bias[col], by = bias[col + 1];
#pragma unroll
            for (int half = 0; half < 2; half++) {
                const int row = m0 + wr * 64 + mt * 16 + g + half * 8;
                float* dst;
                if (MODE == 0) {
                    const int bi = row >> 11;        // SS=2048
                    const int s  = row & (SS - 1);
                    const int h  = col >> 6;         // DK=64
                    const int dk = col & 63;
                    dst = C + (((size_t)(bi * HH + h) * SS + s) * DK + dk);
                } else {
                    dst = C + (size_t)row * N + col;
                }
                float2 o;
                o.x = acc[mt][nt][half * 2 + 0] + bx;
                o.y = acc[mt][nt][half * 2 + 1] + by;
                *(float2*)dst = o;
            }
        }
    }
}

// ---------------------------------------------------------------------------
// Flash attention, fp32 (unchanged from R1: 593us, L1-bound).
// ---------------------------------------------------------------------------
__device__ __forceinline__ int swz(int row, int col) {
    return (row << 6) + ((((col >> 2) ^ (row & 15)) << 2) | (col & 3));
}

__global__ void __launch_bounds__(256) attn_kernel(
    const float* __restrict__ Q, const float* __restrict__ K,
    const float* __restrict__ V, float* __restrict__ ctx)
{
    __shared__ __align__(16) float Qt [64 * 64];
    __shared__ __align__(16) float KtP[64 * 64];
    __shared__ __align__(16) float Vs [64 * 64];

    const int qt = blockIdx.x;
    const int h  = blockIdx.y;
    const int b  = blockIdx.z;
    const int q0 = qt * 64;

    const size_t bh = ((size_t)b * HH + h) * SS * DK;
    const float* Qp = Q + bh + (size_t)q0 * DK;
    const float* Kp = K + bh;
    const float* Vp = V + bh;

    const int tid = threadIdx.x;
    const int tx  = tid & 15;
    const int ty  = tid >> 4;

#pragma unroll
    for (int p = 0; p < 4; p++) {
        const int idx = tid + p * 256;
        const int r   = idx & 63;
        const int d4  = (idx >> 6) << 2;
        float4 v = *(const float4*)(Qp + (r << 6) + d4);
        Qt[swz(d4 + 0, r)] = v.x;
        Qt[swz(d4 + 1, r)] = v.y;
        Qt[swz(d4 + 2, r)] = v.z;
        Qt[swz(d4 + 3, r)] = v.w;
    }

    float m_i[4], l_i[4], acc[4][4];
#pragma unroll
    for (int i = 0; i < 4; i++) {
        m_i[i] = -1e30f; l_i[i] = 0.0f;
#pragma unroll
        for (int j = 0; j < 4; j++) acc[i][j] = 0.0f;
    }

    const int ktmax = qt + 1;
    for (int kt = 0; kt < ktmax; kt++) {
        const float* Kb = Kp + kt * (64 * DK);
        const float* Vb = Vp + kt * (64 * DK);

#pragma unroll
        for (int p = 0; p < 4; p++) {
            const int idx = tid + p * 256;
            const int c   = idx & 63;
            const int d4  = (idx >> 6) << 2;
            float4 kv = *(const float4*)(Kb + (c << 6) + d4);
            KtP[swz(d4 + 0, c)] = kv.x;
            KtP[swz(d4 + 1, c)] = kv.y;
            KtP[swz(d4 + 2, c)] = kv.z;
            KtP[swz(d4 + 3, c)] = kv.w;
            *(float4*)(Vs + idx * 4) = *(const float4*)(Vb + idx * 4);
        }
        __syncthreads();

        float s[4][4];
#pragma unroll
        for (int i = 0; i < 4; i++)
#pragma unroll
            for (int j = 0; j < 4; j++) s[i][j] = 0.0f;

#pragma unroll 16
        for (int d = 0; d < 64; d++) {
            const float4 a  = *(const float4*)&Qt [(d << 6) + ((ty ^ (d & 15)) << 2)];
            const float4 bk = *(const float4*)&KtP[(d << 6) + ((tx ^ (d & 15)) << 2)];
            const float av[4] = {a.x,  a.y,  a.z,  a.w};
            const float bw[4] = {bk.x, bk.y, bk.z, bk.w};
#pragma unroll
            for (int i = 0; i < 4; i++)
#pragma unroll
                for (int j = 0; j < 4; j++)
                    s[i][j] = fmaf(av[i], bw[j], s[i][j]);
        }
        __syncthreads();

#pragma unroll
        for (int i = 0; i < 4; i++) {
            const int qrow  = q0 + ty * 4 + i;
            const int kbase = kt * 64 + tx * 4;
            float sv[4];
#pragma unroll
            for (int j = 0; j < 4; j++)
                sv[j] = (kbase + j <= qrow) ? s[i][j] * 0.125f : -1e9f;

            float mx = fmaxf(fmaxf(sv[0], sv[1]), fmaxf(sv[2], sv[3]));
#pragma unroll
            for (int off = 1; off < 16; off <<= 1)
                mx = fmaxf(mx, __shfl_xor_sync(0xffffffffu, mx, off));

            const float mnew  = fmaxf(m_i[i], mx);
            const float alpha = __expf(m_i[i] - mnew);
            float rs = 0.0f;
#pragma unroll
            for (int j = 0; j < 4; j++) { sv[j] = __expf(sv[j] - mnew); rs += sv[j]; }
#pragma unroll
            for (int off = 1; off < 16; off <<= 1)
                rs += __shfl_xor_sync(0xffffffffu, rs, off);

            l_i[i] = l_i[i] * alpha + rs;
            m_i[i] = mnew;
#pragma unroll
            for (int j = 0; j < 4; j++) acc[i][j] *= alpha;

            *(float4*)&KtP[(ty * 4 + i) * 64 + tx * 4] =
                make_float4(sv[0], sv[1], sv[2], sv[3]);
        }
        __syncthreads();

#pragma unroll 8
        for (int c = 0; c < 64; c++) {
            const float4 bv4 = *(const float4*)&Vs[(c << 6) + (tx << 2)];
            const float aw[4] = {
                KtP[(ty * 4 + 0) * 64 + c],
                KtP[(ty * 4 + 1) * 64 + c],
                KtP[(ty * 4 + 2) * 64 + c],
                KtP[(ty * 4 + 3) * 64 + c]
            };
            const float bw[4] = {bv4.x, bv4.y, bv4.z, bv4.w};
#pragma unroll
            for (int i = 0; i < 4; i++)
#pragma unroll
                for (int j = 0; j < 4; j++)
                    acc[i][j] = fmaf(aw[i], bw[j], acc[i][j]);
        }
        __syncthreads();
    }

#pragma unroll
    for (int i = 0; i < 4; i++) {
        const float inv = 1.0f / l_i[i];
        const int srow  = q0 + ty * 4 + i;
        float* dst = ctx + ((size_t)b * SS + srow) * DDm + h * DK + tx * 4;
        *(float4*)dst = make_float4(acc[i][0] * inv, acc[i][1] * inv,
                                    acc[i][2] * inv, acc[i][3] * inv);
    }
}

// ---------------------------------------------------------------------------
extern "C" void kernel_launch(void* const* d_in, const int* in_sizes, int n_in,
                              void* d_out, int out_size)
{
    const float* q  = (const float*)d_in[0];
    const float* k  = (const float*)d_in[1];
    const float* v  = (const float*)d_in[2];
    // d_in[3] = causal mask (structure applied analytically)
    const float* wq = (const float*)d_in[4];
    const float* bq = (const float*)d_in[5];
    const float* wk = (const float*)d_in[6];
    const float* bk = (const float*)d_in[7];
    const float* wv = (const float*)d_in[8];
    const float* bv = (const float*)d_in[9];
    const float* wo = (const float*)d_in[10];
    const float* bo = (const float*)d_in[11];
    float* out = (float*)d_out;

    float *gq, *gk, *gv, *gctx;
    __nv_bfloat16 *gAh, *gAl, *gWh, *gWl;
    cudaGetSymbolAddress((void**)&gq,   g_Q);
    cudaGetSymbolAddress((void**)&gk,   g_K);
    cudaGetSymbolAddress((void**)&gv,   g_V);
    cudaGetSymbolAddress((void**)&gctx, g_ctx);
    cudaGetSymbolAddress((void**)&gAh,  g_Ah);
    cudaGetSymbolAddress((void**)&gAl,  g_Al);
    cudaGetSymbolAddress((void**)&gWh,  g_Wh);
    cudaGetSymbolAddress((void**)&gWl,  g_Wl);

    cudaFuncSetAttribute(gemm_mma<0>, cudaFuncAttributeMaxDynamicSharedMemorySize,
                         GEMM_SMEM);
    cudaFuncSetAttribute(gemm_mma<1>, cudaFuncAttributeMaxDynamicSharedMemorySize,
                         GEMM_SMEM);

    const int n4w = DDm * DDm / 4;
    const int n4a = MT * DDm / 4;
    const dim3 gsw((n4w + 255) / 256);
    const dim3 gsa((n4a + 255) / 256);
    const dim3 gg(DDm / 128, MT / 128);   // (8, 32)

    // Q projection
    split_kernel<<<gsw, 256>>>((const float4*)wq, (__nv_bfloat162*)gWh, (__nv_bfloat162*)gWl, n4w);
    split_kernel<<<gsa, 256>>>((const float4*)q,  (__nv_bfloat162*)gAh, (__nv_bfloat162*)gAl, n4a);
    gemm_mma<0><<<gg, 256, GEMM_SMEM>>>(gAh, gAl, gWh, gWl, bq, gq, MT, DDm, DDm);

    // K projection
    split_kernel<<<gsw, 256>>>((const float4*)wk, (__nv_bfloat162*)gWh, (__nv_bfloat162*)gWl, n4w);
    split_kernel<<<gsa, 256>>>((const float4*)k,  (__nv_bfloat162*)gAh, (__nv_bfloat162*)gAl, n4a);
    gemm_mma<0><<<gg, 256, GEMM_SMEM>>>(gAh, gAl, gWh, gWl, bk, gk, MT, DDm, DDm);

    // V projection
    split_kernel<<<gsw, 256>>>((const float4*)wv, (__nv_bfloat162*)gWh, (__nv_bfloat162*)gWl, n4w);
    split_kernel<<<gsa, 256>>>((const float4*)v,  (__nv_bfloat162*)gAh, (__nv_bfloat162*)gAl, n4a);
    gemm_mma<0><<<gg, 256, GEMM_SMEM>>>(gAh, gAl, gWh, gWl, bv, gv, MT, DDm, DDm);

    // attention
    attn_kernel<<<dim3(SS / 64, HH, BB), 256>>>(gq, gk, gv, gctx);

    // output projection
    split_kernel<<<gsw, 256>>>((const float4*)wo,  (__nv_bfloat162*)gWh, (__nv_bfloat162*)gWl, n4w);
    split_kernel<<<gsa, 256>>>((const float4*)gctx,(__nv_bfloat162*)gAh, (__nv_bfloat162*)gAl, n4a);
    gemm_mma<1><<<gg, 256, GEMM_SMEM>>>(gAh, gAl, gWh, gWl, bo, out, MT, DDm, DDm);
}

// round 4
// speedup vs baseline: 2.4589x; 1.6769x over previous
#include <cuda_runtime.h>
#include <cuda_bf16.h>
#include <cstdint>

// Problem constants
#define BB  2
#define SS  2048
#define DDm 1024
#define HH  16
#define DK  64
#define MT  (BB*SS)      // 4096

// Scratch (allocation-free: __device__ globals)
__device__ __nv_bfloat16 g_Qh[BB*HH*SS*DK];
__device__ __nv_bfloat16 g_Ql[BB*HH*SS*DK];
__device__ __nv_bfloat16 g_Kh[BB*HH*SS*DK];
__device__ __nv_bfloat16 g_Kl[BB*HH*SS*DK];
__device__ __nv_bfloat16 g_Vh[BB*HH*SS*DK];
__device__ __nv_bfloat16 g_Vl[BB*HH*SS*DK];
__device__ __nv_bfloat16 g_Ah[MT*DDm];
__device__ __nv_bfloat16 g_Al[MT*DDm];
__device__ __nv_bfloat16 g_Wh[DDm*DDm];
__device__ __nv_bfloat16 g_Wl[DDm*DDm];

// ---------------------------------------------------------------------------
// helpers
// ---------------------------------------------------------------------------
__device__ __forceinline__ uint32_t smem_u32(const void* p) {
    uint32_t a;
    asm("{ .reg .u64 t; cvta.to.shared.u64 t, %1; cvt.u32.u64 %0, t; }"
        : "=r"(a) : "l"(p));
    return a;
}

__device__ __forceinline__ void cp16(uint32_t saddr, const void* gaddr) {
    asm volatile("cp.async.cg.shared.global [%0], [%1], 16;"
                 :: "r"(saddr), "l"(gaddr));
}

__device__ __forceinline__ void ldsm4(uint32_t* r, uint32_t addr) {
    asm volatile("ldmatrix.sync.aligned.m8n8.x4.shared.b16 {%0,%1,%2,%3}, [%4];"
                 : "=r"(r[0]), "=r"(r[1]), "=r"(r[2]), "=r"(r[3]) : "r"(addr));
}

__device__ __forceinline__ void ldsm4t(uint32_t* r, uint32_t addr) {
    asm volatile("ldmatrix.sync.aligned.m8n8.x4.trans.shared.b16 {%0,%1,%2,%3}, [%4];"
                 : "=r"(r[0]), "=r"(r[1]), "=r"(r[2]), "=r"(r[3]) : "r"(addr));
}

__device__ __forceinline__ void mma_bf16(float* c, const uint32_t* a,
                                         const uint32_t* b) {
    asm volatile(
        "mma.sync.aligned.m16n8k16.row.col.f32.bf16.bf16.f32 "
        "{%0,%1,%2,%3}, {%4,%5,%6,%7}, {%8,%9}, {%0,%1,%2,%3};"
        : "+f"(c[0]), "+f"(c[1]), "+f"(c[2]), "+f"(c[3])
        : "r"(a[0]), "r"(a[1]), "r"(a[2]), "r"(a[3]), "r"(b[0]), "r"(b[1]));
}

__device__ __forceinline__ float ex2(float x) {
    float r;
    asm("ex2.approx.f32 %0, %1;" : "=f"(r) : "f"(x));
    return r;
}

// ---------------------------------------------------------------------------
// hi/lo bf16 split: h = rn(x), l = rn(x - h)
// ---------------------------------------------------------------------------
__global__ void __launch_bounds__(256) split_kernel(
    const float4* __restrict__ x,
    __nv_bfloat162* __restrict__ hi, __nv_bfloat162* __restrict__ lo, int n4)
{
    int i = blockIdx.x * blockDim.x + threadIdx.x;
    if (i >= n4) return;
    float4 v = x[i];
    __nv_bfloat16 h0 = __float2bfloat16_rn(v.x);
    __nv_bfloat16 h1 = __float2bfloat16_rn(v.y);
    __nv_bfloat16 h2 = __float2bfloat16_rn(v.z);
    __nv_bfloat16 h3 = __float2bfloat16_rn(v.w);
    __nv_bfloat16 l0 = __float2bfloat16_rn(v.x - __bfloat162float(h0));
    __nv_bfloat16 l1 = __float2bfloat16_rn(v.y - __bfloat162float(h1));
    __nv_bfloat16 l2 = __float2bfloat16_rn(v.z - __bfloat162float(h2));
    __nv_bfloat16 l3 = __float2bfloat16_rn(v.w - __bfloat162float(h3));
    hi[2*i]   = __halves2bfloat162(h0, h1);
    hi[2*i+1] = __halves2bfloat162(h2, h3);
    lo[2*i]   = __halves2bfloat162(l0, l1);
    lo[2*i+1] = __halves2bfloat162(l2, l3);
}

// ---------------------------------------------------------------------------
// HMMA GEMM: C = Ah@Wh^T + Ah@Wl^T + Al@Wh^T + bias (bf16 in, fp32 acc)
// MODE 0: write hi/lo bf16 pair in split-head layout [B,H,S,DK] (Ch, Cl)
// MODE 1: write fp32 plain [M,N] (C)
// ---------------------------------------------------------------------------
#define TILE_B   10240              // 128 rows * 80 B
#define STAGE_B  (4 * TILE_B)
#define GEMM_SMEM (2 * STAGE_B)     // 81920

template<int MODE>
__global__ void __launch_bounds__(256) gemm_mma(
    const __nv_bfloat16* __restrict__ Ah, const __nv_bfloat16* __restrict__ Al,
    const __nv_bfloat16* __restrict__ Wh, const __nv_bfloat16* __restrict__ Wl,
    const float* __restrict__ bias, float* __restrict__ C,
    __nv_bfloat16* __restrict__ Ch, __nv_bfloat16* __restrict__ Cl,
    int M, int N, int K)
{
    extern __shared__ __align__(16) char smem[];
    const uint32_t sbase = smem_u32(smem);

    const int tid  = threadIdx.x;
    const int lane = tid & 31;
    const int wid  = tid >> 5;
    const int wr   = wid >> 2;
    const int wc   = wid & 3;
    const int m0   = blockIdx.y * 128;
    const int n0   = blockIdx.x * 128;

    float acc[4][4][4];
#pragma unroll
    for (int i = 0; i < 4; i++)
#pragma unroll
        for (int j = 0; j < 4; j++)
#pragma unroll
            for (int r = 0; r < 4; r++) acc[i][j][r] = 0.0f;

    auto load_chunk = [&](int i, int buf) {
        const int kc0 = i * 32;
        const uint32_t stage = sbase + (uint32_t)buf * STAGE_B;
#pragma unroll
        for (int t = 0; t < 4; t++) {
            const __nv_bfloat16* src = (t == 0) ? Ah : (t == 1) ? Al
                                     : (t == 2) ? Wh : Wl;
            const int r0 = (t < 2) ? m0 : n0;
#pragma unroll
            for (int h = 0; h < 2; h++) {
                const int idx = tid + h * 256;
                const int row = idx >> 2, c = idx & 3;
                cp16(stage + t * TILE_B + row * 80 + c * 16,
                     src + (size_t)(r0 + row) * K + kc0 + c * 8);
            }
        }
    };

    const int mid   = lane >> 3;
    const int lr    = lane & 7;
    const int a_moff = (mid & 1) * 8;
    const int a_koff = (mid >> 1) * 8;
    const int b_noff = (mid >> 1) * 8;
    const int b_koff = (mid & 1) * 8;

    const int NCH = K / 32;

    load_chunk(0, 0);
    asm volatile("cp.async.commit_group;" ::: "memory");

    for (int i = 0; i < NCH; i++) {
        if (i + 1 < NCH) {
            load_chunk(i + 1, (i + 1) & 1);
            asm volatile("cp.async.commit_group;" ::: "memory");
            asm volatile("cp.async.wait_group 1;" ::: "memory");
        } else {
            asm volatile("cp.async.wait_group 0;" ::: "memory");
        }
        __syncthreads();

        const uint32_t stage = sbase + (uint32_t)(i & 1) * STAGE_B;
        const uint32_t tAh = stage;
        const uint32_t tAl = stage + TILE_B;
        const uint32_t tWh = stage + 2 * TILE_B;
        const uint32_t tWl = stage + 3 * TILE_B;

#pragma unroll
        for (int ks = 0; ks < 2; ks++) {
            uint32_t ah[4][4], al[4][4], bh[4][2], bl[4][2];
#pragma unroll
            for (int mt = 0; mt < 4; mt++) {
                const int r  = wr * 64 + mt * 16 + a_moff + lr;
                const int kc = ks * 16 + a_koff;
                ldsm4(ah[mt], tAh + r * 80 + kc * 2);
                ldsm4(al[mt], tAl + r * 80 + kc * 2);
            }
#pragma unroll
            for (int np = 0; np < 2; np++) {
                const int r  = wc * 32 + np * 16 + b_noff + lr;
                const int kc = ks * 16 + b_koff;
                uint32_t t4r[4];
                ldsm4(t4r, tWh + r * 80 + kc * 2);
                bh[2*np][0] = t4r[0]; bh[2*np][1] = t4r[1];
                bh[2*np+1][0] = t4r[2]; bh[2*np+1][1] = t4r[3];
                ldsm4(t4r, tWl + r * 80 + kc * 2);
                bl[2*np][0] = t4r[0]; bl[2*np][1] = t4r[1];
                bl[2*np+1][0] = t4r[2]; bl[2*np+1][1] = t4r[3];
            }
#pragma unroll
            for (int mt = 0; mt < 4; mt++)
#pragma unroll
                for (int nt = 0; nt < 4; nt++) {
                    mma_bf16(acc[mt][nt], ah[mt], bh[nt]);
                    mma_bf16(acc[mt][nt], ah[mt], bl[nt]);
                    mma_bf16(acc[mt][nt], al[mt], bh[nt]);
                }
        }
        __syncthreads();
    }

    const int g  = lane >> 2;
    const int t4 = lane & 3;
#pragma unroll
    for (int mt = 0; mt < 4; mt++) {
#pragma unroll
        for (int nt = 0; nt < 4; nt++) {
            const int col = n0 + wc * 32 + nt * 8 + t4 * 2;
            const float bx = bias[col], by = bias[col + 1];
#pragma unroll
            for (int half = 0; half < 2; half++) {
                const int row = m0 + wr * 64 + mt * 16 + g + half * 8;
                const float v0 = acc[mt][nt][half * 2 + 0] + bx;
                const float v1 = acc[mt][nt][half * 2 + 1] + by;
                if (MODE == 0) {
                    const int bi = row >> 11;
                    const int s  = row & (SS - 1);
                    const int h  = col >> 6;
                    const int dk = col & 63;
                    const size_t idx = (((size_t)(bi * HH + h) * SS + s) * DK + dk);
                    __nv_bfloat16 h0 = __float2bfloat16_rn(v0);
                    __nv_bfloat16 h1 = __float2bfloat16_rn(v1);
                    *(__nv_bfloat162*)(Ch + idx) = __halves2bfloat162(h0, h1);
                    *(__nv_bfloat162*)(Cl + idx) = __halves2bfloat162(
                        __float2bfloat16_rn(v0 - __bfloat162float(h0)),
                        __float2bfloat16_rn(v1 - __bfloat162float(h1)));
                } else {
                    float* dst = C + (size_t)row * N + col;
                    *(float2*)dst = make_float2(v0, v1);
                }
            }
        }
    }
}

// ---------------------------------------------------------------------------
// Flash attention via HMMA. CTA = (b, h, 128 q rows), 8 warps x 16 rows each.
// 64-key steps. 3-term compensated QK^T and PV. P stays in registers.
// Output written as bf16 hi/lo into (Ch, Cl) = (g_Ah, g_Al) in [(b,s), d].
// ---------------------------------------------------------------------------
#define P144 144          // smem row pitch bytes (64 bf16 + 16B pad)
#define ATT_SMEM (128*P144*2 + 64*P144*4)   // Q hi/lo + K,V hi/lo = 73728

__global__ void __launch_bounds__(256) attn_mma(
    const __nv_bfloat16* __restrict__ Qh_, const __nv_bfloat16* __restrict__ Ql_,
    const __nv_bfloat16* __restrict__ Kh_, const __nv_bfloat16* __restrict__ Kl_,
    const __nv_bfloat16* __restrict__ Vh_, const __nv_bfloat16* __restrict__ Vl_,
    __nv_bfloat16* __restrict__ Ch, __nv_bfloat16* __restrict__ Cl)
{
    extern __shared__ __align__(16) char smem[];
    const uint32_t sb = smem_u32(smem);
    const uint32_t oQh = 0,           oQl = 128 * P144;
    const uint32_t oKh = 2*128*P144,  oKl = oKh + 64*P144;
    const uint32_t oVh = oKl + 64*P144, oVl = oVh + 64*P144;

    const int qt = blockIdx.x, h = blockIdx.y, b = blockIdx.z;
    const int q0 = qt * 128;
    const size_t bh = ((size_t)b * HH + h) * SS * DK;

    const int tid  = threadIdx.x;
    const int lane = tid & 31;
    const int wid  = tid >> 5;
    const int wr0  = wid * 16;
    const int g    = lane >> 2;
    const int t4   = lane & 3;
    const int mid  = lane >> 3;
    const int lr   = lane & 7;

    // stage Q (hi/lo), 128 rows x 64 bf16, pitch 144B
    {
        const __nv_bfloat16* sh = Qh_ + bh + (size_t)q0 * DK;
        const __nv_bfloat16* sl = Ql_ + bh + (size_t)q0 * DK;
#pragma unroll
        for (int j = 0; j < 4; j++) {
            const int idx = tid + j * 256;
            const int r = idx >> 3, s = idx & 7;
            *(uint4*)(smem + oQh + r * P144 + s * 16) = *(const uint4*)(sh + r * 64 + s * 8);
            *(uint4*)(smem + oQl + r * P144 + s * 16) = *(const uint4*)(sl + r * 64 + s * 8);
        }
    }

    float m0 = -1e30f, m1 = -1e30f, l0 = 0.0f, l1 = 0.0f;
    float O[8][4];
#pragma unroll
    for (int d = 0; d < 8; d++)
#pragma unroll
        for (int e = 0; e < 4; e++) O[d][e] = 0.0f;

    const uint32_t aoff = (uint32_t)((wr0 + (mid & 1) * 8 + lr) * P144) + (mid >> 1) * 16;
    const uint32_t boff = (uint32_t)(((mid >> 1) * 8 + lr) * P144) + (mid & 1) * 16;

    const int nkt = 2 * (qt + 1);
    const float cs = 0.125f * 1.4426950408889634f;   // scale * log2(e)

    for (int kt = 0; kt < nkt; kt++) {
        __syncthreads();
        // stage K, V (hi/lo): 64 rows x 64 bf16 each
        {
            const __nv_bfloat16* kh = Kh_ + bh + (size_t)kt * 64 * DK;
            const __nv_bfloat16* kl = Kl_ + bh + (size_t)kt * 64 * DK;
            const __nv_bfloat16* vh = Vh_ + bh + (size_t)kt * 64 * DK;
            const __nv_bfloat16* vl = Vl_ + bh + (size_t)kt * 64 * DK;
#pragma unroll
            for (int j = 0; j < 2; j++) {
                const int idx = tid + j * 256;
                const int r = idx >> 3, s = idx & 7;
                const uint32_t so = r * P144 + s * 16;
                const int go = r * 64 + s * 8;
                *(uint4*)(smem + oKh + so) = *(const uint4*)(kh + go);
                *(uint4*)(smem + oKl + so) = *(const uint4*)(kl + go);
                *(uint4*)(smem + oVh + so) = *(const uint4*)(vh + go);
                *(uint4*)(smem + oVl + so) = *(const uint4*)(vl + go);
            }
        }
        __syncthreads();

        if (kt * 64 > q0 + wr0 + 15) continue;   // fully masked for this warp

        // ---- S = Q K^T (3-term) ----
        float S[8][4];
#pragma unroll
        for (int nt = 0; nt < 8; nt++)
#pragma unroll
            for (int e = 0; e < 4; e++) S[nt][e] = 0.0f;

#pragma unroll
        for (int kc = 0; kc < 4; kc++) {
            uint32_t qh[4], ql[4];
            ldsm4(qh, sb + oQh + aoff + kc * 32);
            ldsm4(ql, sb + oQl + aoff + kc * 32);
#pragma unroll
            for (int np = 0; np < 4; np++) {
                const uint32_t bo = boff + (uint32_t)(np * 16 * P144) + kc * 32;
                uint32_t kh4[4], kl4[4];
                ldsm4(kh4, sb + oKh + bo);
                ldsm4(kl4, sb + oKl + bo);
                mma_bf16(S[2*np],   qh, kh4);
                mma_bf16(S[2*np],   qh, kl4);
                mma_bf16(S[2*np],   ql, kh4);
                mma_bf16(S[2*np+1], qh, kh4 + 2);
                mma_bf16(S[2*np+1], qh, kl4 + 2);
                mma_bf16(S[2*np+1], ql, kh4 + 2);
            }
        }

        // ---- online softmax (log2 domain) ----
        const int row0 = q0 + wr0 + g;
        const int row1 = row0 + 8;
        const int kb   = kt * 64 + t4 * 2;
        float mx0 = -1e30f, mx1 = -1e30f;
#pragma unroll
        for (int nt = 0; nt < 8; nt++) {
            const int k0 = kb + nt * 8;
            S[nt][0] = (k0     <= row0) ? S[nt][0] * cs : -1e30f;
            S[nt][1] = (k0 + 1 <= row0) ? S[nt][1] * cs : -1e30f;
            S[nt][2] = (k0     <= row1) ? S[nt][2] * cs : -1e30f;
            S[nt][3] = (k0 + 1 <= row1) ? S[nt][3] * cs : -1e30f;
            mx0 = fmaxf(mx0, fmaxf(S[nt][0], S[nt][1]));
            mx1 = fmaxf(mx1, fmaxf(S[nt][2], S[nt][3]));
        }
        mx0 = fmaxf(mx0, __shfl_xor_sync(0xffffffffu, mx0, 1));
        mx0 = fmaxf(mx0, __shfl_xor_sync(0xffffffffu, mx0, 2));
        mx1 = fmaxf(mx1, __shfl_xor_sync(0xffffffffu, mx1, 1));
        mx1 = fmaxf(mx1, __shfl_xor_sync(0xffffffffu, mx1, 2));

        const float mn0 = fmaxf(m0, mx0);
        const float mn1 = fmaxf(m1, mx1);
        const float a0  = ex2(m0 - mn0);
        const float a1  = ex2(m1 - mn1);
        float rs0 = 0.0f, rs1 = 0.0f;
#pragma unroll
        for (int nt = 0; nt < 8; nt++) {
            S[nt][0] = ex2(S[nt][0] - mn0);
            S[nt][1] = ex2(S[nt][1] - mn0);
            S[nt][2] = ex2(S[nt][2] - mn1);
            S[nt][3] = ex2(S[nt][3] - mn1);
            rs0 += S[nt][0] + S[nt][1];
            rs1 += S[nt][2] + S[nt][3];
        }
        rs0 += __shfl_xor_sync(0xffffffffu, rs0, 1);
        rs0 += __shfl_xor_sync(0xffffffffu, rs0, 2);
        rs1 += __shfl_xor_sync(0xffffffffu, rs1, 1);
        rs1 += __shfl_xor_sync(0xffffffffu, rs1, 2);
        l0 = l0 * a0 + rs0;  m0 = mn0;
        l1 = l1 * a1 + rs1;  m1 = mn1;
#pragma unroll
        for (int d = 0; d < 8; d++) {
            O[d][0] *= a0; O[d][1] *= a0;
            O[d][2] *= a1; O[d][3] *= a1;
        }

        // ---- P -> bf16 hi/lo A-fragments (in registers) ----
        uint32_t Ph[4][4], Pl[4][4];
#pragma unroll
        for (int kc2 = 0; kc2 < 4; kc2++) {
#pragma unroll
            for (int part = 0; part < 2; part++) {
                const int nt = 2 * kc2 + part;
#pragma unroll
                for (int pr = 0; pr < 2; pr++) {
                    const float p0 = S[nt][2*pr + 0];
                    const float p1 = S[nt][2*pr + 1];
                    const __nv_bfloat16 h0 = __float2bfloat16_rn(p0);
                    const __nv_bfloat16 h1 = __float2bfloat16_rn(p1);
                    const __nv_bfloat162 hh = __halves2bfloat162(h0, h1);
                    const __nv_bfloat162 ll = __halves2bfloat162(
                        __float2bfloat16_rn(p0 - __bfloat162float(h0)),
                        __float2bfloat16_rn(p1 - __bfloat162float(h1)));
                    Ph[kc2][part*2 + pr] = *(const uint32_t*)&hh;
                    Pl[kc2][part*2 + pr] = *(const uint32_t*)&ll;
                }
            }
        }

        // ---- O += P V (3-term), V via ldmatrix.trans ----
#pragma unroll
        for (int kc2 = 0; kc2 < 4; kc2++) {
            const uint32_t vrow = (uint32_t)((kc2 * 16 + (mid & 1) * 8 + lr) * P144);
#pragma unroll
            for (int dtp = 0; dtp < 4; dtp++) {
                const uint32_t vo = vrow + (uint32_t)(dtp * 32) + (mid >> 1) * 16;
                uint32_t vh4[4], vl4[4];
                ldsm4t(vh4, sb + oVh + vo);
                ldsm4t(vl4, sb + oVl + vo);
                mma_bf16(O[2*dtp],   Ph[kc2], vh4);
                mma_bf16(O[2*dtp],   Ph[kc2], vl4);
                mma_bf16(O[2*dtp],   Pl[kc2], vh4);
                mma_bf16(O[2*dtp+1], Ph[kc2], vh4 + 2);
                mma_bf16(O[2*dtp+1], Ph[kc2], vl4 + 2);
                mma_bf16(O[2*dtp+1], Pl[kc2], vh4 + 2);
            }
        }
    }

    // ---- epilogue: normalize, write ctx hi/lo in [(b,s), h*64+d] ----
    const float i0 = 1.0f / l0;
    const float i1 = 1.0f / l1;
    const int row0 = q0 + wr0 + g;
    const int colb = h * DK + t4 * 2;
#pragma unroll
    for (int dt = 0; dt < 8; dt++) {
        const int col = colb + dt * 8;
        {
            const float v0 = O[dt][0] * i0, v1 = O[dt][1] * i0;
            const size_t idx = ((size_t)b * SS + row0) * DDm + col;
            const __nv_bfloat16 h0 = __float2bfloat16_rn(v0);
            const __nv_bfloat16 h1 = __float2bfloat16_rn(v1);
            *(__nv_bfloat162*)(Ch + idx) = __halves2bfloat162(h0, h1);
            *(__nv_bfloat162*)(Cl + idx) = __halves2bfloat162(
                __float2bfloat16_rn(v0 - __bfloat162float(h0)),
                __float2bfloat16_rn(v1 - __bfloat162float(h1)));
        }
        {
            const float v0 = O[dt][2] * i1, v1 = O[dt][3] * i1;
            const size_t idx = ((size_t)b * SS + row0 + 8) * DDm + col;
            const __nv_bfloat16 h0 = __float2bfloat16_rn(v0);
            const __nv_bfloat16 h1 = __float2bfloat16_rn(v1);
            *(__nv_bfloat162*)(Ch + idx) = __halves2bfloat162(h0, h1);
            *(__nv_bfloat162*)(Cl + idx) = __halves2bfloat162(
                __float2bfloat16_rn(v0 - __bfloat162float(h0)),
                __float2bfloat16_rn(v1 - __bfloat162float(h1)));
        }
    }
}

// ---------------------------------------------------------------------------
extern "C" void kernel_launch(void* const* d_in, const int* in_sizes, int n_in,
                              void* d_out, int out_size)
{
    const float* q  = (const float*)d_in[0];
    const float* k  = (const float*)d_in[1];
    const float* v  = (const float*)d_in[2];
    // d_in[3] = causal mask (structure applied analytically)
    const float* wq = (const float*)d_in[4];
    const float* bq = (const float*)d_in[5];
    const float* wk = (const float*)d_in[6];
    const float* bk = (const float*)d_in[7];
    const float* wv = (const float*)d_in[8];
    const float* bv = (const float*)d_in[9];
    const float* wo = (const float*)d_in[10];
    const float* bo = (const float*)d_in[11];
    float* out = (float*)d_out;

    __nv_bfloat16 *gQh, *gQl, *gKh, *gKl, *gVh, *gVl, *gAh, *gAl, *gWh, *gWl;
    cudaGetSymbolAddress((void**)&gQh, g_Qh);
    cudaGetSymbolAddress((void**)&gQl, g_Ql);
    cudaGetSymbolAddress((void**)&gKh, g_Kh);
    cudaGetSymbolAddress((void**)&gKl, g_Kl);
    cudaGetSymbolAddress((void**)&gVh, g_Vh);
    cudaGetSymbolAddress((void**)&gVl, g_Vl);
    cudaGetSymbolAddress((void**)&gAh, g_Ah);
    cudaGetSymbolAddress((void**)&gAl, g_Al);
    cudaGetSymbolAddress((void**)&gWh, g_Wh);
    cudaGetSymbolAddress((void**)&gWl, g_Wl);

    cudaFuncSetAttribute(gemm_mma<0>, cudaFuncAttributeMaxDynamicSharedMemorySize, GEMM_SMEM);
    cudaFuncSetAttribute(gemm_mma<1>, cudaFuncAttributeMaxDynamicSharedMemorySize, GEMM_SMEM);
    cudaFuncSetAttribute(attn_mma,    cudaFuncAttributeMaxDynamicSharedMemorySize, ATT_SMEM);

    const int n4w = DDm * DDm / 4;
    const int n4a = MT * DDm / 4;
    const dim3 gsw((n4w + 255) / 256);
    const dim3 gsa((n4a + 255) / 256);
    const dim3 gg(DDm / 128, MT / 128);

    // Q projection
    split_kernel<<<gsw, 256>>>((const float4*)wq, (__nv_bfloat162*)gWh, (__nv_bfloat162*)gWl, n4w);
    split_kernel<<<gsa, 256>>>((const float4*)q,  (__nv_bfloat162*)gAh, (__nv_bfloat162*)gAl, n4a);
    gemm_mma<0><<<gg, 256, GEMM_SMEM>>>(gAh, gAl, gWh, gWl, bq, nullptr, gQh, gQl, MT, DDm, DDm);

    // K projection
    split_kernel<<<gsw, 256>>>((const float4*)wk, (__nv_bfloat162*)gWh, (__nv_bfloat162*)gWl, n4w);
    split_kernel<<<gsa, 256>>>((const float4*)k,  (__nv_bfloat162*)gAh, (__nv_bfloat162*)gAl, n4a);
    gemm_mma<0><<<gg, 256, GEMM_SMEM>>>(gAh, gAl, gWh, gWl, bk, nullptr, gKh, gKl, MT, DDm, DDm);

    // V projection
    split_kernel<<<gsw, 256>>>((const float4*)wv, (__nv_bfloat162*)gWh, (__nv_bfloat162*)gWl, n4w);
    split_kernel<<<gsa, 256>>>((const float4*)v,  (__nv_bfloat162*)gAh, (__nv_bfloat162*)gAl, n4a);
    gemm_mma<0><<<gg, 256, GEMM_SMEM>>>(gAh, gAl, gWh, gWl, bv, nullptr, gVh, gVl, MT, DDm, DDm);

    // attention: writes ctx hi/lo directly into gAh/gAl
    attn_mma<<<dim3(SS / 128, HH, BB), 256, ATT_SMEM>>>(
        gQh, gQl, gKh, gKl, gVh, gVl, gAh, gAl);

    // output projection
    split_kernel<<<gsw, 256>>>((const float4*)wo, (__nv_bfloat162*)gWh, (__nv_bfloat162*)gWl, n4w);
    gemm_mma<1><<<gg, 256, GEMM_SMEM>>>(gAh, gAl, gWh, gWl, bo, out, nullptr, nullptr, MT, DDm, DDm);
}

// round 5
// speedup vs baseline: 2.5323x; 1.0298x over previous
#include <cuda_runtime.h>
#include <cuda_bf16.h>
#include <cstdint>

// Problem constants
#define BB  2
#define SS  2048
#define DDm 1024
#define HH  16
#define DK  64
#define MT  (BB*SS)      // 4096

// Scratch (allocation-free: __device__ globals)
__device__ __nv_bfloat16 g_Qh[BB*HH*SS*DK];
__device__ __nv_bfloat16 g_Ql[BB*HH*SS*DK];
__device__ __nv_bfloat16 g_Kh[BB*HH*SS*DK];
__device__ __nv_bfloat16 g_Kl[BB*HH*SS*DK];
__device__ __nv_bfloat16 g_Vh[BB*HH*SS*DK];
__device__ __nv_bfloat16 g_Vl[BB*HH*SS*DK];
__device__ __nv_bfloat16 g_Ah[MT*DDm];   // attn ctx hi (gemm O input)
__device__ __nv_bfloat16 g_Al[MT*DDm];   // attn ctx lo
// per-input bf16 hi/lo
__device__ __nv_bfloat16 g_Xqh[MT*DDm], g_Xql[MT*DDm];
__device__ __nv_bfloat16 g_Xkh[MT*DDm], g_Xkl[MT*DDm];
__device__ __nv_bfloat16 g_Xvh[MT*DDm], g_Xvl[MT*DDm];
// per-weight bf16 hi/lo
__device__ __nv_bfloat16 g_Wqh[DDm*DDm], g_Wql[DDm*DDm];
__device__ __nv_bfloat16 g_Wkh[DDm*DDm], g_Wkl[DDm*DDm];
__device__ __nv_bfloat16 g_Wvh[DDm*DDm], g_Wvl[DDm*DDm];
__device__ __nv_bfloat16 g_Woh[DDm*DDm], g_Wol[DDm*DDm];

// ---------------------------------------------------------------------------
// helpers
// ---------------------------------------------------------------------------
__device__ __forceinline__ uint32_t smem_u32(const void* p) {
    uint32_t a;
    asm("{ .reg .u64 t; cvta.to.shared.u64 t, %1; cvt.u32.u64 %0, t; }"
        : "=r"(a) : "l"(p));
    return a;
}
__device__ __forceinline__ void cp16(uint32_t saddr, const void* gaddr) {
    asm volatile("cp.async.cg.shared.global [%0], [%1], 16;"
                 :: "r"(saddr), "l"(gaddr));
}
__device__ __forceinline__ void ldsm4(uint32_t* r, uint32_t addr) {
    asm volatile("ldmatrix.sync.aligned.m8n8.x4.shared.b16 {%0,%1,%2,%3}, [%4];"
                 : "=r"(r[0]), "=r"(r[1]), "=r"(r[2]), "=r"(r[3]) : "r"(addr));
}
__device__ __forceinline__ void ldsm4t(uint32_t* r, uint32_t addr) {
    asm volatile("ldmatrix.sync.aligned.m8n8.x4.trans.shared.b16 {%0,%1,%2,%3}, [%4];"
                 : "=r"(r[0]), "=r"(r[1]), "=r"(r[2]), "=r"(r[3]) : "r"(addr));
}
__device__ __forceinline__ void mma_bf16(float* c, const uint32_t* a,
                                         const uint32_t* b) {
    asm volatile(
        "mma.sync.aligned.m16n8k16.row.col.f32.bf16.bf16.f32 "
        "{%0,%1,%2,%3}, {%4,%5,%6,%7}, {%8,%9}, {%0,%1,%2,%3};"
        : "+f"(c[0]), "+f"(c[1]), "+f"(c[2]), "+f"(c[3])
        : "r"(a[0]), "r"(a[1]), "r"(a[2]), "r"(a[3]), "r"(b[0]), "r"(b[1]));
}
__device__ __forceinline__ float ex2(float x) {
    float r;
    asm("ex2.approx.f32 %0, %1;" : "=f"(r) : "f"(x));
    return r;
}

// ---------------------------------------------------------------------------
// fused multi-tensor hi/lo bf16 split (up to 4 segments in one launch)
// ---------------------------------------------------------------------------
__global__ void __launch_bounds__(256) split_multi(
    const float4* __restrict__ x0, const float4* __restrict__ x1,
    const float4* __restrict__ x2, const float4* __restrict__ x3,
    __nv_bfloat162* __restrict__ h0, __nv_bfloat162* __restrict__ l0,
    __nv_bfloat162* __restrict__ h1, __nv_bfloat162* __restrict__ l1,
    __nv_bfloat162* __restrict__ h2, __nv_bfloat162* __restrict__ l2,
    __nv_bfloat162* __restrict__ h3, __nv_bfloat162* __restrict__ l3,
    int n4each, int blocksPer)
{
    const int seg = blockIdx.x / blocksPer;
    const int bid = blockIdx.x % blocksPer;
    const float4* x = (seg == 0) ? x0 : (seg == 1) ? x1 : (seg == 2) ? x2 : x3;
    __nv_bfloat162* hi = (seg == 0) ? h0 : (seg == 1) ? h1 : (seg == 2) ? h2 : h3;
    __nv_bfloat162* lo = (seg == 0) ? l0 : (seg == 1) ? l1 : (seg == 2) ? l2 : l3;

    const int i = bid * blockDim.x + threadIdx.x;
    if (i >= n4each) return;
    float4 v = x[i];
    __nv_bfloat16 a0 = __float2bfloat16_rn(v.x);
    __nv_bfloat16 a1 = __float2bfloat16_rn(v.y);
    __nv_bfloat16 a2 = __float2bfloat16_rn(v.z);
    __nv_bfloat16 a3 = __float2bfloat16_rn(v.w);
    hi[2*i]   = __halves2bfloat162(a0, a1);
    hi[2*i+1] = __halves2bfloat162(a2, a3);
    lo[2*i]   = __halves2bfloat162(
        __float2bfloat16_rn(v.x - __bfloat162float(a0)),
        __float2bfloat16_rn(v.y - __bfloat162float(a1)));
    lo[2*i+1] = __halves2bfloat162(
        __float2bfloat16_rn(v.z - __bfloat162float(a2)),
        __float2bfloat16_rn(v.w - __bfloat162float(a3)));
}

// ---------------------------------------------------------------------------
// HMMA GEMM: C = (Ah@Wh^T + Ah@Wl^T + Al@Wh^T + bias) * oscale
// MODE 0: write hi/lo bf16 pair in split-head layout [B,H,S,DK] (Ch, Cl)
// MODE 1: write fp32 plain [M,N] (C)
// ---------------------------------------------------------------------------
#define TILE_B   10240              // 128 rows * 80 B
#define STAGE_B  (4 * TILE_B)
#define GEMM_SMEM (2 * STAGE_B)     // 81920

template<int MODE>
__global__ void __launch_bounds__(256) gemm_mma(
    const __nv_bfloat16* __restrict__ Ah, const __nv_bfloat16* __restrict__ Al,
    const __nv_bfloat16* __restrict__ Wh, const __nv_bfloat16* __restrict__ Wl,
    const float* __restrict__ bias, float* __restrict__ C,
    __nv_bfloat16* __restrict__ Ch, __nv_bfloat16* __restrict__ Cl,
    float oscale, int M, int N, int K)
{
    extern __shared__ __align__(16) char smem[];
    const uint32_t sbase = smem_u32(smem);

    const int tid  = threadIdx.x;
    const int lane = tid & 31;
    const int wid  = tid >> 5;
    const int wr   = wid >> 2;
    const int wc   = wid & 3;
    const int m0   = blockIdx.y * 128;
    const int n0   = blockIdx.x * 128;

    float acc[4][4][4];
#pragma unroll
    for (int i = 0; i < 4; i++)
#pragma unroll
        for (int j = 0; j < 4; j++)
#pragma unroll
            for (int r = 0; r < 4; r++) acc[i][j][r] = 0.0f;

    auto load_chunk = [&](int i, int buf) {
        const int kc0 = i * 32;
        const uint32_t stage = sbase + (uint32_t)buf * STAGE_B;
#pragma unroll
        for (int t = 0; t < 4; t++) {
            const __nv_bfloat16* src = (t == 0) ? Ah : (t == 1) ? Al
                                     : (t == 2) ? Wh : Wl;
            const int r0 = (t < 2) ? m0 : n0;
#pragma unroll
            for (int h = 0; h < 2; h++) {
                const int idx = tid + h * 256;
                const int row = idx >> 2, c = idx & 3;
                cp16(stage + t * TILE_B + row * 80 + c * 16,
                     src + (size_t)(r0 + row) * K + kc0 + c * 8);
            }
        }
    };

    const int mid   = lane >> 3;
    const int lr    = lane & 7;
    const int a_moff = (mid & 1) * 8;
    const int a_koff = (mid >> 1) * 8;
    const int b_noff = (mid >> 1) * 8;
    const int b_koff = (mid & 1) * 8;

    const int NCH = K / 32;

    load_chunk(0, 0);
    asm volatile("cp.async.commit_group;" ::: "memory");

    for (int i = 0; i < NCH; i++) {
        if (i + 1 < NCH) {
            load_chunk(i + 1, (i + 1) & 1);
            asm volatile("cp.async.commit_group;" ::: "memory");
            asm volatile("cp.async.wait_group 1;" ::: "memory");
        } else {
            asm volatile("cp.async.wait_group 0;" ::: "memory");
        }
        __syncthreads();

        const uint32_t stage = sbase + (uint32_t)(i & 1) * STAGE_B;
        const uint32_t tAh = stage;
        const uint32_t tAl = stage + TILE_B;
        const uint32_t tWh = stage + 2 * TILE_B;
        const uint32_t tWl = stage + 3 * TILE_B;

#pragma unroll
        for (int ks = 0; ks < 2; ks++) {
            uint32_t ah[4][4], al[4][4], bh[4][2], bl[4][2];
#pragma unroll
            for (int mt = 0; mt < 4; mt++) {
                const int r  = wr * 64 + mt * 16 + a_moff + lr;
                const int kc = ks * 16 + a_koff;
                ldsm4(ah[mt], tAh + r * 80 + kc * 2);
                ldsm4(al[mt], tAl + r * 80 + kc * 2);
            }
#pragma unroll
            for (int np = 0; np < 2; np++) {
                const int r  = wc * 32 + np * 16 + b_noff + lr;
                const int kc = ks * 16 + b_koff;
                uint32_t t4r[4];
                ldsm4(t4r, tWh + r * 80 + kc * 2);
                bh[2*np][0] = t4r[0]; bh[2*np][1] = t4r[1];
                bh[2*np+1][0] = t4r[2]; bh[2*np+1][1] = t4r[3];
                ldsm4(t4r, tWl + r * 80 + kc * 2);
                bl[2*np][0] = t4r[0]; bl[2*np][1] = t4r[1];
                bl[2*np+1][0] = t4r[2]; bl[2*np+1][1] = t4r[3];
            }
#pragma unroll
            for (int mt = 0; mt < 4; mt++)
#pragma unroll
                for (int nt = 0; nt < 4; nt++) {
                    mma_bf16(acc[mt][nt], ah[mt], bh[nt]);
                    mma_bf16(acc[mt][nt], ah[mt], bl[nt]);
                    mma_bf16(acc[mt][nt], al[mt], bh[nt]);
                }
        }
        __syncthreads();
    }

    const int g  = lane >> 2;
    const int t4 = lane & 3;
#pragma unroll
    for (int mt = 0; mt < 4; mt++) {
#pragma unroll
        for (int nt = 0; nt < 4; nt++) {
            const int col = n0 + wc * 32 + nt * 8 + t4 * 2;
            const float bx = bias[col], by = bias[col + 1];
#pragma unroll
            for (int half = 0; half < 2; half++) {
                const int row = m0 + wr * 64 + mt * 16 + g + half * 8;
                const float v0 = (acc[mt][nt][half * 2 + 0] + bx) * oscale;
                const float v1 = (acc[mt][nt][half * 2 + 1] + by) * oscale;
                if (MODE == 0) {
                    const int bi = row >> 11;
                    const int s  = row & (SS - 1);
                    const int h  = col >> 6;
                    const int dk = col & 63;
                    const size_t idx = (((size_t)(bi * HH + h) * SS + s) * DK + dk);
                    __nv_bfloat16 h0 = __float2bfloat16_rn(v0);
                    __nv_bfloat16 h1 = __float2bfloat16_rn(v1);
                    *(__nv_bfloat162*)(Ch + idx) = __halves2bfloat162(h0, h1);
                    *(__nv_bfloat162*)(Cl + idx) = __halves2bfloat162(
                        __float2bfloat16_rn(v0 - __bfloat162float(h0)),
                        __float2bfloat16_rn(v1 - __bfloat162float(h1)));
                } else {
                    float* dst = C + (size_t)row * N + col;
                    *(float2*)dst = make_float2(v0, v1);
                }
            }
        }
    }
}

// ---------------------------------------------------------------------------
// Flash attention via HMMA. CTA = (b, h, 128 q rows), 8 warps x 16 rows.
// Q pre-scaled by 0.125*log2(e) in projection; Q fragments hoisted to regs.
// K/V hi/lo cp.async double-buffered. Reverse qt order (heavy CTAs first).
// ---------------------------------------------------------------------------
#define P144 144
#define KV_T   (64 * P144)              // one tensor tile: 9216 B
#define KV_ST  (4 * KV_T)               // Kh,Kl,Vh,Vl: 36864 B
#define Q_BYTES (2 * 128 * P144)        // 36864 B
#define ATT_SMEM (Q_BYTES + 2 * KV_ST)  // 110592

__global__ void __launch_bounds__(256) attn_mma(
    const __nv_bfloat16* __restrict__ Qh_, const __nv_bfloat16* __restrict__ Ql_,
    const __nv_bfloat16* __restrict__ Kh_, const __nv_bfloat16* __restrict__ Kl_,
    const __nv_bfloat16* __restrict__ Vh_, const __nv_bfloat16* __restrict__ Vl_,
    __nv_bfloat16* __restrict__ Ch, __nv_bfloat16* __restrict__ Cl)
{
    extern __shared__ __align__(16) char smem[];
    const uint32_t sb = smem_u32(smem);
    const uint32_t oQh = 0, oQl = 128 * P144;

    const int qt = (int)gridDim.x - 1 - (int)blockIdx.x;  // heavy tiles first
    const int h = blockIdx.y, b = blockIdx.z;
    const int q0 = qt * 128;
    const size_t bh = ((size_t)b * HH + h) * SS * DK;

    const int tid  = threadIdx.x;
    const int lane = tid & 31;
    const int wid  = tid >> 5;
    const int wr0  = wid * 16;
    const int g    = lane >> 2;
    const int t4   = lane & 3;
    const int mid  = lane >> 3;
    const int lr   = lane & 7;

    const int nkt = 2 * (qt + 1);

    // cp.async loader for one K/V stage (Kh,Kl,Vh,Vl: 64 x 64 bf16 each)
    auto load_kv = [&](int kt, int buf) {
        const uint32_t stage = sb + Q_BYTES + (uint32_t)buf * KV_ST;
        const size_t go = bh + (size_t)kt * 64 * DK;
        const __nv_bfloat16* srcs[4] = {Kh_ + go, Kl_ + go, Vh_ + go, Vl_ + go};
#pragma unroll
        for (int t = 0; t < 4; t++) {
#pragma unroll
            for (int j = 0; j < 2; j++) {
                const int idx = tid + j * 256;
                const int r = idx >> 3, s = idx & 7;
                cp16(stage + t * KV_T + r * P144 + s * 16, srcs[t] + r * 64 + s * 8);
            }
        }
    };

    // prefetch kt=0
    load_kv(0, 0);
    asm volatile("cp.async.commit_group;" ::: "memory");

    // stage Q to smem (regular stores), then hoist fragments to registers
    {
        const __nv_bfloat16* sh = Qh_ + bh + (size_t)q0 * DK;
        const __nv_bfloat16* sl = Ql_ + bh + (size_t)q0 * DK;
#pragma unroll
        for (int j = 0; j < 4; j++) {
            const int idx = tid + j * 256;
            const int r = idx >> 3, s = idx & 7;
            *(uint4*)(smem + oQh + r * P144 + s * 16) = *(const uint4*)(sh + r * 64 + s * 8);
            *(uint4*)(smem + oQl + r * P144 + s * 16) = *(const uint4*)(sl + r * 64 + s * 8);
        }
    }
    __syncthreads();

    const uint32_t aoff = (uint32_t)((wr0 + (mid & 1) * 8 + lr) * P144) + (mid >> 1) * 16;
    uint32_t qh[4][4], ql[4][4];
#pragma unroll
    for (int kc = 0; kc < 4; kc++) {
        ldsm4(qh[kc], sb + oQh + aoff + kc * 32);
        ldsm4(ql[kc], sb + oQl + aoff + kc * 32);
    }

    float m0 = -1e30f, m1 = -1e30f, l0 = 0.0f, l1 = 0.0f;
    float O[8][4];
#pragma unroll
    for (int d = 0; d < 8; d++)
#pragma unroll
        for (int e = 0; e < 4; e++) O[d][e] = 0.0f;

    const uint32_t boff = (uint32_t)(((mid >> 1) * 8 + lr) * P144) + (mid & 1) * 16;

    for (int kt = 0; kt < nkt; kt++) {
        if (kt + 1 < nkt) {
            load_kv(kt + 1, (kt + 1) & 1);
            asm volatile("cp.async.commit_group;" ::: "memory");
            asm volatile("cp.async.wait_group 1;" ::: "memory");
        } else {
            asm volatile("cp.async.wait_group 0;" ::: "memory");
        }
        __syncthreads();

        if (kt * 64 <= q0 + wr0 + 15) {   // warp not fully masked
            const uint32_t stage = sb + Q_BYTES + (uint32_t)(kt & 1) * KV_ST;
            const uint32_t sKh = stage, sKl = stage + KV_T;
            const uint32_t sVh = stage + 2 * KV_T, sVl = stage + 3 * KV_T;

            // ---- S = Q K^T (3-term); Q already scaled by 0.125*log2e ----
            float S[8][4];
#pragma unroll
            for (int nt = 0; nt < 8; nt++)
#pragma unroll
                for (int e = 0; e < 4; e++) S[nt][e] = 0.0f;

#pragma unroll
            for (int kc = 0; kc < 4; kc++) {
#pragma unroll
                for (int np = 0; np < 4; np++) {
                    const uint32_t bo = boff + (uint32_t)(np * 16 * P144) + kc * 32;
                    uint32_t kh4[4], kl4[4];
                    ldsm4(kh4, sKh + bo);
                    ldsm4(kl4, sKl + bo);
                    mma_bf16(S[2*np],   qh[kc], kh4);
                    mma_bf16(S[2*np],   qh[kc], kl4);
                    mma_bf16(S[2*np],   ql[kc], kh4);
                    mma_bf16(S[2*np+1], qh[kc], kh4 + 2);
                    mma_bf16(S[2*np+1], qh[kc], kl4 + 2);
                    mma_bf16(S[2*np+1], ql[kc], kh4 + 2);
                }
            }

            // ---- online softmax (log2 domain; Q pre-scaled) ----
            const int row0 = q0 + wr0 + g;
            const int row1 = row0 + 8;
            float mx0 = -1e30f, mx1 = -1e30f;
            if (kt * 64 + 63 <= q0 + wr0) {
                // fully unmasked tile for this warp
#pragma unroll
                for (int nt = 0; nt < 8; nt++) {
                    mx0 = fmaxf(mx0, fmaxf(S[nt][0], S[nt][1]));
                    mx1 = fmaxf(mx1, fmaxf(S[nt][2], S[nt][3]));
                }
            } else {
                const int kb = kt * 64 + t4 * 2;
#pragma unroll
                for (int nt = 0; nt < 8; nt++) {
                    const int k0 = kb + nt * 8;
                    S[nt][0] = (k0     <= row0) ? S[nt][0] : -1e30f;
                    S[nt][1] = (k0 + 1 <= row0) ? S[nt][1] : -1e30f;
                    S[nt][2] = (k0     <= row1) ? S[nt][2] : -1e30f;
                    S[nt][3] = (k0 + 1 <= row1) ? S[nt][3] : -1e30f;
                    mx0 = fmaxf(mx0, fmaxf(S[nt][0], S[nt][1]));
                    mx1 = fmaxf(mx1, fmaxf(S[nt][2], S[nt][3]));
                }
            }
            mx0 = fmaxf(mx0, __shfl_xor_sync(0xffffffffu, mx0, 1));
            mx0 = fmaxf(mx0, __shfl_xor_sync(0xffffffffu, mx0, 2));
            mx1 = fmaxf(mx1, __shfl_xor_sync(0xffffffffu, mx1, 1));
            mx1 = fmaxf(mx1, __shfl_xor_sync(0xffffffffu, mx1, 2));

            const float mn0 = fmaxf(m0, mx0);
            const float mn1 = fmaxf(m1, mx1);
            const float a0  = ex2(m0 - mn0);
            const float a1  = ex2(m1 - mn1);
            float rs0 = 0.0f, rs1 = 0.0f;
#pragma unroll
            for (int nt = 0; nt < 8; nt++) {
                S[nt][0] = ex2(S[nt][0] - mn0);
                S[nt][1] = ex2(S[nt][1] - mn0);
                S[nt][2] = ex2(S[nt][2] - mn1);
                S[nt][3] = ex2(S[nt][3] - mn1);
                rs0 += S[nt][0] + S[nt][1];
                rs1 += S[nt][2] + S[nt][3];
            }
            rs0 += __shfl_xor_sync(0xffffffffu, rs0, 1);
            rs0 += __shfl_xor_sync(0xffffffffu, rs0, 2);
            rs1 += __shfl_xor_sync(0xffffffffu, rs1, 1);
            rs1 += __shfl_xor_sync(0xffffffffu, rs1, 2);
            l0 = l0 * a0 + rs0;  m0 = mn0;
            l1 = l1 * a1 + rs1;  m1 = mn1;
#pragma unroll
            for (int d = 0; d < 8; d++) {
                O[d][0] *= a0; O[d][1] *= a0;
                O[d][2] *= a1; O[d][3] *= a1;
            }

            // ---- P -> bf16 hi/lo A-fragments ----
            uint32_t Ph[4][4], Pl[4][4];
#pragma unroll
            for (int kc2 = 0; kc2 < 4; kc2++) {
#pragma unroll
                for (int part = 0; part < 2; part++) {
                    const int nt = 2 * kc2 + part;
#pragma unroll
                    for (int pr = 0; pr < 2; pr++) {
                        const float p0 = S[nt][2*pr + 0];
                        const float p1 = S[nt][2*pr + 1];
                        const __nv_bfloat16 h0 = __float2bfloat16_rn(p0);
                        const __nv_bfloat16 h1 = __float2bfloat16_rn(p1);
                        const __nv_bfloat162 hh = __halves2bfloat162(h0, h1);
                        const __nv_bfloat162 ll = __halves2bfloat162(
                            __float2bfloat16_rn(p0 - __bfloat162float(h0)),
                            __float2bfloat16_rn(p1 - __bfloat162float(h1)));
                        Ph[kc2][part*2 + pr] = *(const uint32_t*)&hh;
                        Pl[kc2][part*2 + pr] = *(const uint32_t*)&ll;
                    }
                }
            }

            // ---- O += P V (3-term), V via ldmatrix.trans ----
#pragma unroll
            for (int kc2 = 0; kc2 < 4; kc2++) {
                const uint32_t vrow = (uint32_t)((kc2 * 16 + (mid & 1) * 8 + lr) * P144);
#pragma unroll
                for (int dtp = 0; dtp < 4; dtp++) {
                    const uint32_t vo = vrow + (uint32_t)(dtp * 32) + (mid >> 1) * 16;
                    uint32_t vh4[4], vl4[4];
                    ldsm4t(vh4, sVh + vo);
                    ldsm4t(vl4, sVl + vo);
                    mma_bf16(O[2*dtp],   Ph[kc2], vh4);
                    mma_bf16(O[2*dtp],   Ph[kc2], vl4);
                    mma_bf16(O[2*dtp],   Pl[kc2], vh4);
                    mma_bf16(O[2*dtp+1], Ph[kc2], vh4 + 2);
                    mma_bf16(O[2*dtp+1], Ph[kc2], vl4 + 2);
                    mma_bf16(O[2*dtp+1], Pl[kc2], vh4 + 2);
                }
            }
        }
        __syncthreads();
    }

    // ---- epilogue: normalize, write ctx hi/lo in [(b,s), h*64+d] ----
    const float i0 = 1.0f / l0;
    const float i1 = 1.0f / l1;
    const int row0 = q0 + wr0 + g;
    const int colb = h * DK + t4 * 2;
#pragma unroll
    for (int dt = 0; dt < 8; dt++) {
        const int col = colb + dt * 8;
        {
            const float v0 = O[dt][0] * i0, v1 = O[dt][1] * i0;
            const size_t idx = ((size_t)b * SS + row0) * DDm + col;
            const __nv_bfloat16 h0 = __float2bfloat16_rn(v0);
            const __nv_bfloat16 h1 = __float2bfloat16_rn(v1);
            *(__nv_bfloat162*)(Ch + idx) = __halves2bfloat162(h0, h1);
            *(__nv_bfloat162*)(Cl + idx) = __halves2bfloat162(
                __float2bfloat16_rn(v0 - __bfloat162float(h0)),
                __float2bfloat16_rn(v1 - __bfloat162float(h1)));
        }
        {
            const float v0 = O[dt][2] * i1, v1 = O[dt][3] * i1;
            const size_t idx = ((size_t)b * SS + row0 + 8) * DDm + col;
            const __nv_bfloat16 h0 = __float2bfloat16_rn(v0);
            const __nv_bfloat16 h1 = __float2bfloat16_rn(v1);
            *(__nv_bfloat162*)(Ch + idx) = __halves2bfloat162(h0, h1);
            *(__nv_bfloat162*)(Cl + idx) = __halves2bfloat162(
                __float2bfloat16_rn(v0 - __bfloat162float(h0)),
                __float2bfloat16_rn(v1 - __bfloat162float(h1)));
        }
    }
}

// ---------------------------------------------------------------------------
extern "C" void kernel_launch(void* const* d_in, const int* in_sizes, int n_in,
                              void* d_out, int out_size)
{
    const float* q  = (const float*)d_in[0];
    const float* k  = (const float*)d_in[1];
    const float* v  = (const float*)d_in[2];
    // d_in[3] = causal mask (structure applied analytically)
    const float* wq = (const float*)d_in[4];
    const float* bq = (const float*)d_in[5];
    const float* wk = (const float*)d_in[6];
    const float* bk = (const float*)d_in[7];
    const float* wv = (const float*)d_in[8];
    const float* bv = (const float*)d_in[9];
    const float* wo = (const float*)d_in[10];
    const float* bo = (const float*)d_in[11];
    float* out = (float*)d_out;

    __nv_bfloat16 *gQh, *gQl, *gKh, *gKl, *gVh, *gVl, *gAh, *gAl;
    __nv_bfloat16 *gXqh, *gXql, *gXkh, *gXkl, *gXvh, *gXvl;
    __nv_bfloat16 *gWqh, *gWql, *gWkh, *gWkl, *gWvh, *gWvl, *gWoh, *gWol;
    cudaGetSymbolAddress((void**)&gQh, g_Qh);   cudaGetSymbolAddress((void**)&gQl, g_Ql);
    cudaGetSymbolAddress((void**)&gKh, g_Kh);   cudaGetSymbolAddress((void**)&gKl, g_Kl);
    cudaGetSymbolAddress((void**)&gVh, g_Vh);   cudaGetSymbolAddress((void**)&gVl, g_Vl);
    cudaGetSymbolAddress((void**)&gAh, g_Ah);   cudaGetSymbolAddress((void**)&gAl, g_Al);
    cudaGetSymbolAddress((void**)&gXqh, g_Xqh); cudaGetSymbolAddress((void**)&gXql, g_Xql);
    cudaGetSymbolAddress((void**)&gXkh, g_Xkh); cudaGetSymbolAddress((void**)&gXkl, g_Xkl);
    cudaGetSymbolAddress((void**)&gXvh, g_Xvh); cudaGetSymbolAddress((void**)&gXvl, g_Xvl);
    cudaGetSymbolAddress((void**)&gWqh, g_Wqh); cudaGetSymbolAddress((void**)&gWql, g_Wql);
    cudaGetSymbolAddress((void**)&gWkh, g_Wkh); cudaGetSymbolAddress((void**)&gWkl, g_Wkl);
    cudaGetSymbolAddress((void**)&gWvh, g_Wvh); cudaGetSymbolAddress((void**)&gWvl, g_Wvl);
    cudaGetSymbolAddress((void**)&gWoh, g_Woh); cudaGetSymbolAddress((void**)&gWol, g_Wol);

    cudaFuncSetAttribute(gemm_mma<0>, cudaFuncAttributeMaxDynamicSharedMemorySize, GEMM_SMEM);
    cudaFuncSetAttribute(gemm_mma<1>, cudaFuncAttributeMaxDynamicSharedMemorySize, GEMM_SMEM);
    cudaFuncSetAttribute(attn_mma,    cudaFuncAttributeMaxDynamicSharedMemorySize, ATT_SMEM);

    const float cs = 0.125f * 1.4426950408889634f;   // 1/sqrt(DK) * log2(e)

    // 1) split all 4 weights in one launch
    {
        const int n4 = DDm * DDm / 4;          // 262144
        const int bp = (n4 + 255) / 256;       // 1024
        split_multi<<<4 * bp, 256>>>(
            (const float4*)wq, (const float4*)wk, (const float4*)wv, (const float4*)wo,
            (__nv_bfloat162*)gWqh, (__nv_bfloat162*)gWql,
            (__nv_bfloat162*)gWkh, (__nv_bfloat162*)gWkl,
            (__nv_bfloat162*)gWvh, (__nv_bfloat162*)gWvl,
            (__nv_bfloat162*)gWoh, (__nv_bfloat162*)gWol,
            n4, bp);
    }
    // 2) split q,k,v inputs in one launch
    {
        const int n4 = MT * DDm / 4;           // 1048576
        const int bp = (n4 + 255) / 256;       // 4096
        split_multi<<<3 * bp, 256>>>(
            (const float4*)q, (const float4*)k, (const float4*)v, (const float4*)q,
            (__nv_bfloat162*)gXqh, (__nv_bfloat162*)gXql,
            (__nv_bfloat162*)gXkh, (__nv_bfloat162*)gXkl,
            (__nv_bfloat162*)gXvh, (__nv_bfloat162*)gXvl,
            (__nv_bfloat162*)gXqh, (__nv_bfloat162*)gXql,   // unused seg 3
            n4, bp);
    }

    const dim3 gg(DDm / 128, MT / 128);   // (8, 32)

    // 3) projections (Q pre-scaled by cs)
    gemm_mma<0><<<gg, 256, GEMM_SMEM>>>(gXqh, gXql, gWqh, gWql, bq, nullptr,
                                        gQh, gQl, cs,   MT, DDm, DDm);
    gemm_mma<0><<<gg, 256, GEMM_SMEM>>>(gXkh, gXkl, gWkh, gWkl, bk, nullptr,
                                        gKh, gKl, 1.0f, MT, DDm, DDm);
    gemm_mma<0><<<gg, 256, GEMM_SMEM>>>(gXvh, gXvl, gWvh, gWvl, bv, nullptr,
                                        gVh, gVl, 1.0f, MT, DDm, DDm);

    // 4) attention -> ctx hi/lo in gAh/gAl
    attn_mma<<<dim3(SS / 128, HH, BB), 256, ATT_SMEM>>>(
        gQh, gQl, gKh, gKl, gVh, gVl, gAh, gAl);

    // 5) output projection
    gemm_mma<1><<<gg, 256, GEMM_SMEM>>>(gAh, gAl, gWoh, gWol, bo, out,
                                        nullptr, nullptr, 1.0f, MT, DDm, DDm);
}

// round 6
// speedup vs baseline: 2.5366x; 1.0017x over previous
#include <cuda_runtime.h>
#include <cuda_bf16.h>
#include <cstdint>

// Problem constants
#define BB  2
#define SS  2048
#define DDm 1024
#define HH  16
#define DK  64
#define MT  (BB*SS)      // 4096

// Scratch (allocation-free: __device__ globals)
__device__ __nv_bfloat16 g_Qh[BB*HH*SS*DK];
__device__ __nv_bfloat16 g_Ql[BB*HH*SS*DK];
__device__ __nv_bfloat16 g_Kh[BB*HH*SS*DK];
__device__ __nv_bfloat16 g_Kl[BB*HH*SS*DK];
__device__ __nv_bfloat16 g_Vh[BB*HH*SS*DK];
__device__ __nv_bfloat16 g_Vl[BB*HH*SS*DK];
__device__ __nv_bfloat16 g_Ah[MT*DDm];   // attn ctx hi (gemm O input)
__device__ __nv_bfloat16 g_Al[MT*DDm];   // attn ctx lo
// per-input bf16 hi/lo
__device__ __nv_bfloat16 g_Xqh[MT*DDm], g_Xql[MT*DDm];
__device__ __nv_bfloat16 g_Xkh[MT*DDm], g_Xkl[MT*DDm];
__device__ __nv_bfloat16 g_Xvh[MT*DDm], g_Xvl[MT*DDm];
// per-weight bf16 hi/lo
__device__ __nv_bfloat16 g_Wqh[DDm*DDm], g_Wql[DDm*DDm];
__device__ __nv_bfloat16 g_Wkh[DDm*DDm], g_Wkl[DDm*DDm];
__device__ __nv_bfloat16 g_Wvh[DDm*DDm], g_Wvl[DDm*DDm];
__device__ __nv_bfloat16 g_Woh[DDm*DDm], g_Wol[DDm*DDm];

// ---------------------------------------------------------------------------
// helpers
// ---------------------------------------------------------------------------
__device__ __forceinline__ uint32_t smem_u32(const void* p) {
    uint32_t a;
    asm("{ .reg .u64 t; cvta.to.shared.u64 t, %1; cvt.u32.u64 %0, t; }"
        : "=r"(a) : "l"(p));
    return a;
}
__device__ __forceinline__ void cp16(uint32_t saddr, const void* gaddr) {
    asm volatile("cp.async.cg.shared.global [%0], [%1], 16;"
                 :: "r"(saddr), "l"(gaddr));
}
__device__ __forceinline__ void ldsm4(uint32_t* r, uint32_t addr) {
    asm volatile("ldmatrix.sync.aligned.m8n8.x4.shared.b16 {%0,%1,%2,%3}, [%4];"
                 : "=r"(r[0]), "=r"(r[1]), "=r"(r[2]), "=r"(r[3]) : "r"(addr));
}
__device__ __forceinline__ void ldsm4t(uint32_t* r, uint32_t addr) {
    asm volatile("ldmatrix.sync.aligned.m8n8.x4.trans.shared.b16 {%0,%1,%2,%3}, [%4];"
                 : "=r"(r[0]), "=r"(r[1]), "=r"(r[2]), "=r"(r[3]) : "r"(addr));
}
__device__ __forceinline__ void mma_bf16(float* c, const uint32_t* a,
                                         const uint32_t* b) {
    asm volatile(
        "mma.sync.aligned.m16n8k16.row.col.f32.bf16.bf16.f32 "
        "{%0,%1,%2,%3}, {%4,%5,%6,%7}, {%8,%9}, {%0,%1,%2,%3};"
        : "+f"(c[0]), "+f"(c[1]), "+f"(c[2]), "+f"(c[3])
        : "r"(a[0]), "r"(a[1]), "r"(a[2]), "r"(a[3]), "r"(b[0]), "r"(b[1]));
}
__device__ __forceinline__ float ex2(float x) {
    float r;
    asm("ex2.approx.f32 %0, %1;" : "=f"(r) : "f"(x));
    return r;
}

// ---------------------------------------------------------------------------
// fused multi-tensor hi/lo bf16 split (up to 4 segments in one launch)
// ---------------------------------------------------------------------------
__global__ void __launch_bounds__(256) split_multi(
    const float4* __restrict__ x0, const float4* __restrict__ x1,
    const float4* __restrict__ x2, const float4* __restrict__ x3,
    __nv_bfloat162* __restrict__ h0, __nv_bfloat162* __restrict__ l0,
    __nv_bfloat162* __restrict__ h1, __nv_bfloat162* __restrict__ l1,
    __nv_bfloat162* __restrict__ h2, __nv_bfloat162* __restrict__ l2,
    __nv_bfloat162* __restrict__ h3, __nv_bfloat162* __restrict__ l3,
    int n4each, int blocksPer)
{
    const int seg = blockIdx.x / blocksPer;
    const int bid = blockIdx.x % blocksPer;
    const float4* x = (seg == 0) ? x0 : (seg == 1) ? x1 : (seg == 2) ? x2 : x3;
    __nv_bfloat162* hi = (seg == 0) ? h0 : (seg == 1) ? h1 : (seg == 2) ? h2 : h3;
    __nv_bfloat162* lo = (seg == 0) ? l0 : (seg == 1) ? l1 : (seg == 2) ? l2 : l3;

    const int i = bid * blockDim.x + threadIdx.x;
    if (i >= n4each) return;
    float4 v = x[i];
    __nv_bfloat16 a0 = __float2bfloat16_rn(v.x);
    __nv_bfloat16 a1 = __float2bfloat16_rn(v.y);
    __nv_bfloat16 a2 = __float2bfloat16_rn(v.z);
    __nv_bfloat16 a3 = __float2bfloat16_rn(v.w);
    hi[2*i]   = __halves2bfloat162(a0, a1);
    hi[2*i+1] = __halves2bfloat162(a2, a3);
    lo[2*i]   = __halves2bfloat162(
        __float2bfloat16_rn(v.x - __bfloat162float(a0)),
        __float2bfloat16_rn(v.y - __bfloat162float(a1)));
    lo[2*i+1] = __halves2bfloat162(
        __float2bfloat16_rn(v.z - __bfloat162float(a2)),
        __float2bfloat16_rn(v.w - __bfloat162float(a3)));
}

// ---------------------------------------------------------------------------
// HMMA GEMM: C = (Ah@Wh^T + Ah@Wl^T + Al@Wh^T + bias) * oscale
// 128 threads (4 warps), warp tile 64x64, CTA 128x128, BK=32, double buffer.
// MODE 0: write hi/lo bf16 pair in split-head layout [B,H,S,DK] (Ch, Cl)
// MODE 1: write fp32 plain [M,N] (C)
// ---------------------------------------------------------------------------
#define TILE_B   10240              // 128 rows * 80 B
#define STAGE_B  (4 * TILE_B)
#define GEMM_SMEM (2 * STAGE_B)     // 81920

template<int MODE>
__global__ void __launch_bounds__(128) gemm_mma(
    const __nv_bfloat16* __restrict__ Ah, const __nv_bfloat16* __restrict__ Al,
    const __nv_bfloat16* __restrict__ Wh, const __nv_bfloat16* __restrict__ Wl,
    const float* __restrict__ bias, float* __restrict__ C,
    __nv_bfloat16* __restrict__ Ch, __nv_bfloat16* __restrict__ Cl,
    float oscale, int M, int N, int K)
{
    extern __shared__ __align__(16) char smem[];
    const uint32_t sbase = smem_u32(smem);

    const int tid  = threadIdx.x;
    const int lane = tid & 31;
    const int wid  = tid >> 5;        // 0..3
    const int wr   = wid >> 1;        // 0..1 (64-row slab)
    const int wc   = wid & 1;         // 0..1 (64-col slab)
    const int m0   = blockIdx.y * 128;
    const int n0   = blockIdx.x * 128;

    float acc[4][8][4];
#pragma unroll
    for (int i = 0; i < 4; i++)
#pragma unroll
        for (int j = 0; j < 8; j++)
#pragma unroll
            for (int r = 0; r < 4; r++) acc[i][j][r] = 0.0f;

    // loader: 4 tiles * (128 rows x 32 cols bf16 = 64B = 4x16B), 16 cp/thread
    auto load_chunk = [&](int i, int buf) {
        const int kc0 = i * 32;
        const uint32_t stage = sbase + (uint32_t)buf * STAGE_B;
#pragma unroll
        for (int t = 0; t < 4; t++) {
            const __nv_bfloat16* src = (t == 0) ? Ah : (t == 1) ? Al
                                     : (t == 2) ? Wh : Wl;
            const int r0 = (t < 2) ? m0 : n0;
#pragma unroll
            for (int h = 0; h < 4; h++) {
                const int idx = tid + h * 128;
                const int row = idx >> 2, c = idx & 3;
                cp16(stage + t * TILE_B + row * 80 + c * 16,
                     src + (size_t)(r0 + row) * K + kc0 + c * 8);
            }
        }
    };

    const int mid = lane >> 3;
    const int lr  = lane & 7;
    const int a_moff = (mid & 1) * 8;
    const int a_koff = (mid >> 1) * 8;
    const int b_noff = (mid >> 1) * 8;
    const int b_koff = (mid & 1) * 8;

    const int NCH = K / 32;

    load_chunk(0, 0);
    asm volatile("cp.async.commit_group;" ::: "memory");

    for (int i = 0; i < NCH; i++) {
        if (i + 1 < NCH) {
            load_chunk(i + 1, (i + 1) & 1);
            asm volatile("cp.async.commit_group;" ::: "memory");
            asm volatile("cp.async.wait_group 1;" ::: "memory");
        } else {
            asm volatile("cp.async.wait_group 0;" ::: "memory");
        }
        __syncthreads();

        const uint32_t stage = sbase + (uint32_t)(i & 1) * STAGE_B;
        const uint32_t tAh = stage;
        const uint32_t tAl = stage + TILE_B;
        const uint32_t tWh = stage + 2 * TILE_B;
        const uint32_t tWl = stage + 3 * TILE_B;

#pragma unroll
        for (int ks = 0; ks < 2; ks++) {
            uint32_t ah[4][4], al[4][4], bh[8][2], bl[8][2];
#pragma unroll
            for (int mt = 0; mt < 4; mt++) {
                const int r  = wr * 64 + mt * 16 + a_moff + lr;
                const int kc = ks * 16 + a_koff;
                ldsm4(ah[mt], tAh + r * 80 + kc * 2);
                ldsm4(al[mt], tAl + r * 80 + kc * 2);
            }
#pragma unroll
            for (int np = 0; np < 4; np++) {
                const int r  = wc * 64 + np * 16 + b_noff + lr;
                const int kc = ks * 16 + b_koff;
                uint32_t t4r[4];
                ldsm4(t4r, tWh + r * 80 + kc * 2);
                bh[2*np][0] = t4r[0]; bh[2*np][1] = t4r[1];
                bh[2*np+1][0] = t4r[2]; bh[2*np+1][1] = t4r[3];
                ldsm4(t4r, tWl + r * 80 + kc * 2);
                bl[2*np][0] = t4r[0]; bl[2*np][1] = t4r[1];
                bl[2*np+1][0] = t4r[2]; bl[2*np+1][1] = t4r[3];
            }
#pragma unroll
            for (int mt = 0; mt < 4; mt++)
#pragma unroll
                for (int nt = 0; nt < 8; nt++) {
                    mma_bf16(acc[mt][nt], ah[mt], bh[nt]);
                    mma_bf16(acc[mt][nt], ah[mt], bl[nt]);
                    mma_bf16(acc[mt][nt], al[mt], bh[nt]);
                }
        }
        __syncthreads();
    }

    const int g  = lane >> 2;
    const int t4 = lane & 3;
#pragma unroll
    for (int mt = 0; mt < 4; mt++) {
#pragma unroll
        for (int nt = 0; nt < 8; nt++) {
            const int col = n0 + wc * 64 + nt * 8 + t4 * 2;
            const float bx = bias[col], by = bias[col + 1];
#pragma unroll
            for (int half = 0; half < 2; half++) {
                const int row = m0 + wr * 64 + mt * 16 + g + half * 8;
                const float v0 = (acc[mt][nt][half * 2 + 0] + bx) * oscale;
                const float v1 = (acc[mt][nt][half * 2 + 1] + by) * oscale;
                if (MODE == 0) {
                    const int bi = row >> 11;
                    const int s  = row & (SS - 1);
                    const int h  = col >> 6;
                    const int dk = col & 63;
                    const size_t idx = (((size_t)(bi * HH + h) * SS + s) * DK + dk);
                    __nv_bfloat16 h0 = __float2bfloat16_rn(v0);
                    __nv_bfloat16 h1 = __float2bfloat16_rn(v1);
                    *(__nv_bfloat162*)(Ch + idx) = __halves2bfloat162(h0, h1);
                    *(__nv_bfloat162*)(Cl + idx) = __halves2bfloat162(
                        __float2bfloat16_rn(v0 - __bfloat162float(h0)),
                        __float2bfloat16_rn(v1 - __bfloat162float(h1)));
                } else {
                    float* dst = C + (size_t)row * N + col;
                    *(float2*)dst = make_float2(v0, v1);
                }
            }
        }
    }
}

// ---------------------------------------------------------------------------
// Flash attention via HMMA (unchanged from R5).
// ---------------------------------------------------------------------------
#define P144 144
#define KV_T   (64 * P144)
#define KV_ST  (4 * KV_T)
#define Q_BYTES (2 * 128 * P144)
#define ATT_SMEM (Q_BYTES + 2 * KV_ST)   // 110592

__global__ void __launch_bounds__(256) attn_mma(
    const __nv_bfloat16* __restrict__ Qh_, const __nv_bfloat16* __restrict__ Ql_,
    const __nv_bfloat16* __restrict__ Kh_, const __nv_bfloat16* __restrict__ Kl_,
    const __nv_bfloat16* __restrict__ Vh_, const __nv_bfloat16* __restrict__ Vl_,
    __nv_bfloat16* __restrict__ Ch, __nv_bfloat16* __restrict__ Cl)
{
    extern __shared__ __align__(16) char smem[];
    const uint32_t sb = smem_u32(smem);
    const uint32_t oQh = 0, oQl = 128 * P144;

    const int qt = (int)gridDim.x - 1 - (int)blockIdx.x;
    const int h = blockIdx.y, b = blockIdx.z;
    const int q0 = qt * 128;
    const size_t bh = ((size_t)b * HH + h) * SS * DK;

    const int tid  = threadIdx.x;
    const int lane = tid & 31;
    const int wid  = tid >> 5;
    const int wr0  = wid * 16;
    const int g    = lane >> 2;
    const int t4   = lane & 3;
    const int mid  = lane >> 3;
    const int lr   = lane & 7;

    const int nkt = 2 * (qt + 1);

    auto load_kv = [&](int kt, int buf) {
        const uint32_t stage = sb + Q_BYTES + (uint32_t)buf * KV_ST;
        const size_t go = bh + (size_t)kt * 64 * DK;
        const __nv_bfloat16* srcs[4] = {Kh_ + go, Kl_ + go, Vh_ + go, Vl_ + go};
#pragma unroll
        for (int t = 0; t < 4; t++) {
#pragma unroll
            for (int j = 0; j < 2; j++) {
                const int idx = tid + j * 256;
                const int r = idx >> 3, s = idx & 7;
                cp16(stage + t * KV_T + r * P144 + s * 16, srcs[t] + r * 64 + s * 8);
            }
        }
    };

    load_kv(0, 0);
    asm volatile("cp.async.commit_group;" ::: "memory");

    {
        const __nv_bfloat16* sh = Qh_ + bh + (size_t)q0 * DK;
        const __nv_bfloat16* sl = Ql_ + bh + (size_t)q0 * DK;
#pragma unroll
        for (int j = 0; j < 4; j++) {
            const int idx = tid + j * 256;
            const int r = idx >> 3, s = idx & 7;
            *(uint4*)(smem + oQh + r * P144 + s * 16) = *(const uint4*)(sh + r * 64 + s * 8);
            *(uint4*)(smem + oQl + r * P144 + s * 16) = *(const uint4*)(sl + r * 64 + s * 8);
        }
    }
    __syncthreads();

    const uint32_t aoff = (uint32_t)((wr0 + (mid & 1) * 8 + lr) * P144) + (mid >> 1) * 16;
    uint32_t qh[4][4], ql[4][4];
#pragma unroll
    for (int kc = 0; kc < 4; kc++) {
        ldsm4(qh[kc], sb + oQh + aoff + kc * 32);
        ldsm4(ql[kc], sb + oQl + aoff + kc * 32);
    }

    float m0 = -1e30f, m1 = -1e30f, l0 = 0.0f, l1 = 0.0f;
    float O[8][4];
#pragma unroll
    for (int d = 0; d < 8; d++)
#pragma unroll
        for (int e = 0; e < 4; e++) O[d][e] = 0.0f;

    const uint32_t boff = (uint32_t)(((mid >> 1) * 8 + lr) * P144) + (mid & 1) * 16;

    for (int kt = 0; kt < nkt; kt++) {
        if (kt + 1 < nkt) {
            load_kv(kt + 1, (kt + 1) & 1);
            asm volatile("cp.async.commit_group;" ::: "memory");
            asm volatile("cp.async.wait_group 1;" ::: "memory");
        } else {
            asm volatile("cp.async.wait_group 0;" ::: "memory");
        }
        __syncthreads();

        if (kt * 64 <= q0 + wr0 + 15) {
            const uint32_t stage = sb + Q_BYTES + (uint32_t)(kt & 1) * KV_ST;
            const uint32_t sKh = stage, sKl = stage + KV_T;
            const uint32_t sVh = stage + 2 * KV_T, sVl = stage + 3 * KV_T;

            float S[8][4];
#pragma unroll
            for (int nt = 0; nt < 8; nt++)
#pragma unroll
                for (int e = 0; e < 4; e++) S[nt][e] = 0.0f;

#pragma unroll
            for (int kc = 0; kc < 4; kc++) {
#pragma unroll
                for (int np = 0; np < 4; np++) {
                    const uint32_t bo = boff + (uint32_t)(np * 16 * P144) + kc * 32;
                    uint32_t kh4[4], kl4[4];
                    ldsm4(kh4, sKh + bo);
                    ldsm4(kl4, sKl + bo);
                    mma_bf16(S[2*np],   qh[kc], kh4);
                    mma_bf16(S[2*np],   qh[kc], kl4);
                    mma_bf16(S[2*np],   ql[kc], kh4);
                    mma_bf16(S[2*np+1], qh[kc], kh4 + 2);
                    mma_bf16(S[2*np+1], qh[kc], kl4 + 2);
                    mma_bf16(S[2*np+1], ql[kc], kh4 + 2);
                }
            }

            const int row0 = q0 + wr0 + g;
            const int row1 = row0 + 8;
            float mx0 = -1e30f, mx1 = -1e30f;
            if (kt * 64 + 63 <= q0 + wr0) {
#pragma unroll
                for (int nt = 0; nt < 8; nt++) {
                    mx0 = fmaxf(mx0, fmaxf(S[nt][0], S[nt][1]));
                    mx1 = fmaxf(mx1, fmaxf(S[nt][2], S[nt][3]));
                }
            } else {
                const int kb = kt * 64 + t4 * 2;
#pragma unroll
                for (int nt = 0; nt < 8; nt++) {
                    const int k0 = kb + nt * 8;
                    S[nt][0] = (k0     <= row0) ? S[nt][0] : -1e30f;
                    S[nt][1] = (k0 + 1 <= row0) ? S[nt][1] : -1e30f;
                    S[nt][2] = (k0     <= row1) ? S[nt][2] : -1e30f;
                    S[nt][3] = (k0 + 1 <= row1) ? S[nt][3] : -1e30f;
                    mx0 = fmaxf(mx0, fmaxf(S[nt][0], S[nt][1]));
                    mx1 = fmaxf(mx1, fmaxf(S[nt][2], S[nt][3]));
                }
            }
            mx0 = fmaxf(mx0, __shfl_xor_sync(0xffffffffu, mx0, 1));
            mx0 = fmaxf(mx0, __shfl_xor_sync(0xffffffffu, mx0, 2));
            mx1 = fmaxf(mx1, __shfl_xor_sync(0xffffffffu, mx1, 1));
            mx1 = fmaxf(mx1, __shfl_xor_sync(0xffffffffu, mx1, 2));

            const float mn0 = fmaxf(m0, mx0);
            const float mn1 = fmaxf(m1, mx1);
            const float a0  = ex2(m0 - mn0);
            const float a1  = ex2(m1 - mn1);
            float rs0 = 0.0f, rs1 = 0.0f;
#pragma unroll
            for (int nt = 0; nt < 8; nt++) {
                S[nt][0] = ex2(S[nt][0] - mn0);
                S[nt][1] = ex2(S[nt][1] - mn0);
                S[nt][2] = ex2(S[nt][2] - mn1);
                S[nt][3] = ex2(S[nt][3] - mn1);
                rs0 += S[nt][0] + S[nt][1];
                rs1 += S[nt][2] + S[nt][3];
            }
            rs0 += __shfl_xor_sync(0xffffffffu, rs0, 1);
            rs0 += __shfl_xor_sync(0xffffffffu, rs0, 2);
            rs1 += __shfl_xor_sync(0xffffffffu, rs1, 1);
            rs1 += __shfl_xor_sync(0xffffffffu, rs1, 2);
            l0 = l0 * a0 + rs0;  m0 = mn0;
            l1 = l1 * a1 + rs1;  m1 = mn1;
#pragma unroll
            for (int d = 0; d < 8; d++) {
                O[d][0] *= a0; O[d][1] *= a0;
                O[d][2] *= a1; O[d][3] *= a1;
            }

            uint32_t Ph[4][4], Pl[4][4];
#pragma unroll
            for (int kc2 = 0; kc2 < 4; kc2++) {
#pragma unroll
                for (int part = 0; part < 2; part++) {
                    const int nt = 2 * kc2 + part;
#pragma unroll
                    for (int pr = 0; pr < 2; pr++) {
                        const float p0 = S[nt][2*pr + 0];
                        const float p1 = S[nt][2*pr + 1];
                        const __nv_bfloat16 h0 = __float2bfloat16_rn(p0);
                        const __nv_bfloat16 h1 = __float2bfloat16_rn(p1);
                        const __nv_bfloat162 hh = __halves2bfloat162(h0, h1);
                        const __nv_bfloat162 ll = __halves2bfloat162(
                            __float2bfloat16_rn(p0 - __bfloat162float(h0)),
                            __float2bfloat16_rn(p1 - __bfloat162float(h1)));
                        Ph[kc2][part*2 + pr] = *(const uint32_t*)&hh;
                        Pl[kc2][part*2 + pr] = *(const uint32_t*)&ll;
                    }
                }
            }

#pragma unroll
            for (int kc2 = 0; kc2 < 4; kc2++) {
                const uint32_t vrow = (uint32_t)((kc2 * 16 + (mid & 1) * 8 + lr) * P144);
#pragma unroll
                for (int dtp = 0; dtp < 4; dtp++) {
                    const uint32_t vo = vrow + (uint32_t)(dtp * 32) + (mid >> 1) * 16;
                    uint32_t vh4[4], vl4[4];
                    ldsm4t(vh4, sVh + vo);
                    ldsm4t(vl4, sVl + vo);
                    mma_bf16(O[2*dtp],   Ph[kc2], vh4);
                    mma_bf16(O[2*dtp],   Ph[kc2], vl4);
                    mma_bf16(O[2*dtp],   Pl[kc2], vh4);
                    mma_bf16(O[2*dtp+1], Ph[kc2], vh4 + 2);
                    mma_bf16(O[2*dtp+1], Ph[kc2], vl4 + 2);
                    mma_bf16(O[2*dtp+1], Pl[kc2], vh4 + 2);
                }
            }
        }
        __syncthreads();
    }

    const float i0 = 1.0f / l0;
    const float i1 = 1.0f / l1;
    const int row0 = q0 + wr0 + g;
    const int colb = h * DK + t4 * 2;
#pragma unroll
    for (int dt = 0; dt < 8; dt++) {
        const int col = colb + dt * 8;
        {
            const float v0 = O[dt][0] * i0, v1 = O[dt][1] * i0;
            const size_t idx = ((size_t)b * SS + row0) * DDm + col;
            const __nv_bfloat16 h0 = __float2bfloat16_rn(v0);
            const __nv_bfloat16 h1 = __float2bfloat16_rn(v1);
            *(__nv_bfloat162*)(Ch + idx) = __halves2bfloat162(h0, h1);
            *(__nv_bfloat162*)(Cl + idx) = __halves2bfloat162(
                __float2bfloat16_rn(v0 - __bfloat162float(h0)),
                __float2bfloat16_rn(v1 - __bfloat162float(h1)));
        }
        {
            const float v0 = O[dt][2] * i1, v1 = O[dt][3] * i1;
            const size_t idx = ((size_t)b * SS + row0 + 8) * DDm + col;
            const __nv_bfloat16 h0 = __float2bfloat16_rn(v0);
            const __nv_bfloat16 h1 = __float2bfloat16_rn(v1);
            *(__nv_bfloat162*)(Ch + idx) = __halves2bfloat162(h0, h1);
            *(__nv_bfloat162*)(Cl + idx) = __halves2bfloat162(
                __float2bfloat16_rn(v0 - __bfloat162float(h0)),
                __float2bfloat16_rn(v1 - __bfloat162float(h1)));
        }
    }
}

// ---------------------------------------------------------------------------
extern "C" void kernel_launch(void* const* d_in, const int* in_sizes, int n_in,
                              void* d_out, int out_size)
{
    const float* q  = (const float*)d_in[0];
    const float* k  = (const float*)d_in[1];
    const float* v  = (const float*)d_in[2];
    // d_in[3] = causal mask (structure applied analytically)
    const float* wq = (const float*)d_in[4];
    const float* bq = (const float*)d_in[5];
    const float* wk = (const float*)d_in[6];
    const float* bk = (const float*)d_in[7];
    const float* wv = (const float*)d_in[8];
    const float* bv = (const float*)d_in[9];
    const float* wo = (const float*)d_in[10];
    const float* bo = (const float*)d_in[11];
    float* out = (float*)d_out;

    __nv_bfloat16 *gQh, *gQl, *gKh, *gKl, *gVh, *gVl, *gAh, *gAl;
    __nv_bfloat16 *gXqh, *gXql, *gXkh, *gXkl, *gXvh, *gXvl;
    __nv_bfloat16 *gWqh, *gWql, *gWkh, *gWkl, *gWvh, *gWvl, *gWoh, *gWol;
    cudaGetSymbolAddress((void**)&gQh, g_Qh);   cudaGetSymbolAddress((void**)&gQl, g_Ql);
    cudaGetSymbolAddress((void**)&gKh, g_Kh);   cudaGetSymbolAddress((void**)&gKl, g_Kl);
    cudaGetSymbolAddress((void**)&gVh, g_Vh);   cudaGetSymbolAddress((void**)&gVl, g_Vl);
    cudaGetSymbolAddress((void**)&gAh, g_Ah);   cudaGetSymbolAddress((void**)&gAl, g_Al);
    cudaGetSymbolAddress((void**)&gXqh, g_Xqh); cudaGetSymbolAddress((void**)&gXql, g_Xql);
    cudaGetSymbolAddress((void**)&gXkh, g_Xkh); cudaGetSymbolAddress((void**)&gXkl, g_Xkl);
    cudaGetSymbolAddress((void**)&gXvh, g_Xvh); cudaGetSymbolAddress((void**)&gXvl, g_Xvl);
    cudaGetSymbolAddress((void**)&gWqh, g_Wqh); cudaGetSymbolAddress((void**)&gWql, g_Wql);
    cudaGetSymbolAddress((void**)&gWkh, g_Wkh); cudaGetSymbolAddress((void**)&gWkl, g_Wkl);
    cudaGetSymbolAddress((void**)&gWvh, g_Wvh); cudaGetSymbolAddress((void**)&gWvl, g_Wvl);
    cudaGetSymbolAddress((void**)&gWoh, g_Woh); cudaGetSymbolAddress((void**)&gWol, g_Wol);

    cudaFuncSetAttribute(gemm_mma<0>, cudaFuncAttributeMaxDynamicSharedMemorySize, GEMM_SMEM);
    cudaFuncSetAttribute(gemm_mma<1>, cudaFuncAttributeMaxDynamicSharedMemorySize, GEMM_SMEM);
    cudaFuncSetAttribute(attn_mma,    cudaFuncAttributeMaxDynamicSharedMemorySize, ATT_SMEM);

    const float cs = 0.125f * 1.4426950408889634f;   // 1/sqrt(DK) * log2(e)

    // 1) split all 4 weights in one launch
    {
        const int n4 = DDm * DDm / 4;
        const int bp = (n4 + 255) / 256;
        split_multi<<<4 * bp, 256>>>(
            (const float4*)wq, (const float4*)wk, (const float4*)wv, (const float4*)wo,
            (__nv_bfloat162*)gWqh, (__nv_bfloat162*)gWql,
            (__nv_bfloat162*)gWkh, (__nv_bfloat162*)gWkl,
            (__nv_bfloat162*)gWvh, (__nv_bfloat162*)gWvl,
            (__nv_bfloat162*)gWoh, (__nv_bfloat162*)gWol,
            n4, bp);
    }
    // 2) split q,k,v inputs in one launch
    {
        const int n4 = MT * DDm / 4;
        const int bp = (n4 + 255) / 256;
        split_multi<<<3 * bp, 256>>>(
            (const float4*)q, (const float4*)k, (const float4*)v, (const float4*)q,
            (__nv_bfloat162*)gXqh, (__nv_bfloat162*)gXql,
            (__nv_bfloat162*)gXkh, (__nv_bfloat162*)gXkl,
            (__nv_bfloat162*)gXvh, (__nv_bfloat162*)gXvl,
            (__nv_bfloat162*)gXqh, (__nv_bfloat162*)gXql,
            n4, bp);
    }

    const dim3 gg(DDm / 128, MT / 128);   // (8, 32)

    // 3) projections (Q pre-scaled by cs)
    gemm_mma<0><<<gg, 128, GEMM_SMEM>>>(gXqh, gXql, gWqh, gWql, bq, nullptr,
                                        gQh, gQl, cs,   MT, DDm, DDm);
    gemm_mma<0><<<gg, 128, GEMM_SMEM>>>(gXkh, gXkl, gWkh, gWkl, bk, nullptr,
                                        gKh, gKl, 1.0f, MT, DDm, DDm);
    gemm_mma<0><<<gg, 128, GEMM_SMEM>>>(gXvh, gXvl, gWvh, gWvl, bv, nullptr,
                                        gVh, gVl, 1.0f, MT, DDm, DDm);

    // 4) attention -> ctx hi/lo in gAh/gAl
    attn_mma<<<dim3(SS / 128, HH, BB), 256, ATT_SMEM>>>(
        gQh, gQl, gKh, gKl, gVh, gVl, gAh, gAl);

    // 5) output projection
    gemm_mma<1><<<gg, 128, GEMM_SMEM>>>(gAh, gAl, gWoh, gWol, bo, out,
                                        nullptr, nullptr, 1.0f, MT, DDm, DDm);
}